// round 10
// baseline (speedup 1.0000x reference)
#include <cuda_runtime.h>
#include <cuda_bf16.h>
#include <math.h>
#include <stdint.h>

#define BSZ 2
#define SL  2048
#define DM  1024
#define NH  16
#define HD  64
#define MR  (BSZ * SL)   // 4096 rows

__device__ float g_qkv[(size_t)MR * 3 * DM];   // 48 MB
__device__ float g_o  [(size_t)MR * DM];       // 16 MB (tf32-rounded o)
__device__ float g_xr [(size_t)MR * DM];       // 16 MB (tf32-rounded x)
__device__ float g_wT [(size_t)3 * DM * DM + (size_t)DM * DM]; // rounded, transposed weights
__device__ float g_l  [(size_t)BSZ * NH * SL]; // softmax denominators

// ---------------------------------------------------------------------------
__device__ __forceinline__ float to_tf32(float x) {
    asm("cvt.rna.tf32.f32 %0, %0;" : "+f"(x));
    return x;
}

__device__ __forceinline__ void mma_tf32(float c[4], const float a0, const float a1,
                                         const float a2, const float a3,
                                         const float b0, const float b1) {
    asm volatile(
        "mma.sync.aligned.m16n8k8.row.col.f32.tf32.tf32.f32 "
        "{%0,%1,%2,%3}, {%4,%5,%6,%7}, {%8,%9}, {%0,%1,%2,%3};"
        : "+f"(c[0]), "+f"(c[1]), "+f"(c[2]), "+f"(c[3])
        : "r"(__float_as_uint(a0)), "r"(__float_as_uint(a1)),
          "r"(__float_as_uint(a2)), "r"(__float_as_uint(a3)),
          "r"(__float_as_uint(b0)), "r"(__float_as_uint(b1)));
}

__device__ __forceinline__ void mma_bf16(float c[4], uint32_t a0, uint32_t a1,
                                         uint32_t a2, uint32_t a3,
                                         uint32_t b0, uint32_t b1) {
    asm volatile(
        "mma.sync.aligned.m16n8k16.row.col.f32.bf16.bf16.f32 "
        "{%0,%1,%2,%3}, {%4,%5,%6,%7}, {%8,%9}, {%0,%1,%2,%3};"
        : "+f"(c[0]), "+f"(c[1]), "+f"(c[2]), "+f"(c[3])
        : "r"(a0), "r"(a1), "r"(a2), "r"(a3), "r"(b0), "r"(b1));
}

__device__ __forceinline__ uint32_t pack_bf16(float a, float b) {
    __nv_bfloat162 t = __floats2bfloat162_rn(a, b);
    return *(uint32_t*)&t;
}

__device__ __forceinline__ uint32_t smem_u32(const void* p) {
    uint32_t a;
    asm("{ .reg .u64 t; cvta.to.shared.u64 t, %1; cvt.u32.u64 %0, t; }"
        : "=r"(a) : "l"(p));
    return a;
}

__device__ __forceinline__ void cp_async16(uint32_t dst, const void* src) {
    asm volatile("cp.async.ca.shared.global [%0], [%1], 16;"
                 :: "r"(dst), "l"(src));
}
__device__ __forceinline__ void cp_commit() {
    asm volatile("cp.async.commit_group;");
}
template <int N>
__device__ __forceinline__ void cp_wait() {
    asm volatile("cp.async.wait_group %0;" :: "n"(N));
}

#define P32(k) ((((k) & 3) * 8) + (((k) >> 2) & 7) + ((k) & 32))
#define PPOS(j) ((((j) & 3) << 1) | (((j) & 7) >> 2))

// ---------------------------------------------------------------------------
// prep kernels
// ---------------------------------------------------------------------------
__global__ __launch_bounds__(256) void round_tf32_kernel(
    const float* __restrict__ src, float* __restrict__ dst, int n4)
{
    int i = blockIdx.x * 256 + threadIdx.x;
    if (i < n4) {
        float4 v = *(const float4*)(src + 4 * (size_t)i);
        v.x = to_tf32(v.x); v.y = to_tf32(v.y);
        v.z = to_tf32(v.z); v.w = to_tf32(v.w);
        *(float4*)(dst + 4 * (size_t)i) = v;
    }
}

__global__ __launch_bounds__(256) void transpose_round32(
    const float* __restrict__ src, float* __restrict__ dst, int R, int Cc)
{
    __shared__ float t[32][33];
    int r0 = blockIdx.y * 32, c0 = blockIdx.x * 32;
    int tx = threadIdx.x, ty = threadIdx.y;
#pragma unroll
    for (int j = 0; j < 32; j += 8)
        t[ty + j][tx] = to_tf32(src[(size_t)(r0 + ty + j) * Cc + c0 + tx]);
    __syncthreads();
#pragma unroll
    for (int j = 0; j < 32; j += 8)
        dst[(size_t)(c0 + ty + j) * R + r0 + tx] = t[tx][ty + j];
}

// ---------------------------------------------------------------------------
// TF32 GEMM v2 (unchanged from Round 9): C = A @ Bt^T, 128x256x32,
// 256 thr, warp tile 64x64, cp.async double-buffered.
// ---------------------------------------------------------------------------
#define GS_A (128 * 40)
#define GS_B (256 * 40)
#define GS_STAGE (GS_A + GS_B)
#define GEMM2_SMEM (2 * GS_STAGE * 4)

__global__ __launch_bounds__(256) void mma_gemm2(
    const float* __restrict__ A, const float* __restrict__ Bt,
    float* __restrict__ C, int M, int N, int K)
{
    extern __shared__ float gsm[];
    uint32_t sb = smem_u32(gsm);

    int tid  = threadIdx.x;
    int lane = tid & 31, warp = tid >> 5;
    int g = lane >> 2, tg = lane & 3;
    int wm = (warp & 1) * 64;
    int wn = (warp >> 1) * 64;
    int bm = blockIdx.y * 128, bn = blockIdx.x * 256;

    float c[4][8][4];
#pragma unroll
    for (int mt = 0; mt < 4; mt++)
#pragma unroll
        for (int nt = 0; nt < 8; nt++)
#pragma unroll
            for (int i = 0; i < 4; i++) c[mt][nt][i] = 0.f;

#define G2_ISSUE(S, K0)                                                        \
    {                                                                          \
        uint32_t abase = sb + (S) * GS_STAGE * 4;                              \
        uint32_t bbase = abase + GS_A * 4;                                     \
        _Pragma("unroll")                                                      \
        for (int i = 0; i < 4; i++) {                                          \
            int id = tid + 256 * i;                                            \
            int r = id >> 3, k4 = id & 7;                                      \
            cp_async16(abase + r * 160 + k4 * 16,                              \
                       A + (size_t)(bm + r) * K + (K0) + 4 * k4);              \
        }                                                                      \
        _Pragma("unroll")                                                      \
        for (int i = 0; i < 8; i++) {                                          \
            int id = tid + 256 * i;                                            \
            int n = id >> 3, k4 = id & 7;                                      \
            cp_async16(bbase + n * 160 + k4 * 16,                              \
                       Bt + (size_t)(bn + n) * K + (K0) + 4 * k4);             \
        }                                                                      \
        cp_commit();                                                           \
    }

    G2_ISSUE(0, 0);

    int nch = K / 32;
    for (int ch = 0; ch < nch; ch++) {
        int s = ch & 1;
        if (ch + 1 < nch) {
            G2_ISSUE(s ^ 1, (ch + 1) * 32);
            cp_wait<1>();
        } else {
            cp_wait<0>();
        }
        __syncthreads();

        const float* As = gsm + s * GS_STAGE;
        const float* Bs = As + GS_A;

#pragma unroll
        for (int j = 0; j < 4; j++) {
            int kc = 8 * j + 2 * tg;
            float2 af[4][2];
#pragma unroll
            for (int mt = 0; mt < 4; mt++) {
                int rl = wm + mt * 16 + g;
                af[mt][0] = *(const float2*)(As + rl * 40 + kc);
                af[mt][1] = *(const float2*)(As + (rl + 8) * 40 + kc);
            }
#pragma unroll
            for (int nt = 0; nt < 8; nt++) {
                float2 bf = *(const float2*)(Bs + (wn + nt * 8 + g) * 40 + kc);
#pragma unroll
                for (int mt = 0; mt < 4; mt++)
                    mma_tf32(c[mt][nt], af[mt][0].x, af[mt][1].x,
                             af[mt][0].y, af[mt][1].y, bf.x, bf.y);
            }
        }
        __syncthreads();
    }

#pragma unroll
    for (int mt = 0; mt < 4; mt++)
#pragma unroll
        for (int nt = 0; nt < 8; nt++) {
            int row = bm + wm + mt * 16 + g;
            int col = bn + wn + nt * 8 + 2 * tg;
            *(float2*)(C + (size_t)row * N + col) =
                make_float2(c[mt][nt][0], c[mt][nt][1]);
            *(float2*)(C + (size_t)(row + 8) * N + col) =
                make_float2(c[mt][nt][2], c[mt][nt][3]);
        }
}

// ---------------------------------------------------------------------------
// Single-pass causal attention v2: q-block 256 rows, 8 warps, warp tile 32
// q-rows (two 16-row subtiles processed sequentially to cap registers).
// QK = bf16 3-term split; PV = tf32. Unnormalized w + l; o scaled in-kernel.
// ---------------------------------------------------------------------------
#define QB 256
// byte offsets in dynamic smem
#define QHI_OFF 0                       // u32[256*40]
#define QLO_OFF 40960
#define KHI_OFF 81920                   // u32[64*40]
#define KLO_OFF 92160
#define SV_OFF  102400                  // float[64*68]
#define SP_OFF  119808                  // float[256*68]
#define ATTN_SMEM 189440
#define BTS 40

__global__ __launch_bounds__(256) void attn_sp(
    const float* __restrict__ qkv, float* __restrict__ w_out,
    float* __restrict__ o_out, float* __restrict__ l_out)
{
    extern __shared__ char smc[];
    uint32_t* sqhi = (uint32_t*)(smc + QHI_OFF);
    uint32_t* sqlo = (uint32_t*)(smc + QLO_OFF);
    uint32_t* skhi = (uint32_t*)(smc + KHI_OFF);
    uint32_t* sklo = (uint32_t*)(smc + KLO_OFF);
    float*    sv   = (float*)(smc + SV_OFF);
    float*    sp   = (float*)(smc + SP_OFF);

    int tid  = threadIdx.x;
    int lane = tid & 31, warp = tid >> 5;
    int g = lane >> 2, tg = lane & 3;
    int wq = warp * 32;                        // warp q-offset within block
    int qt = (gridDim.x - 1) - blockIdx.x;     // heavy-first
    int h = blockIdx.y, b = blockIdx.z;
    int q0 = qt * QB;
    int ktv = 4 * qt + 3;                      // last k-tile touching the band
    const float scale = 0.125f;

    const float* qb = qkv + (size_t)b * SL * 3 * DM + (size_t)h * HD;
    const float* kb = qb + DM;
    const float* vb = qb + 2 * DM;

    // ---- stage Q hi/lo (256 rows x 64 d), permuted-pair bf16 layout ----
#pragma unroll
    for (int i = 0; i < 16; i++) {
        int idx = tid + i * 256;
        int r = idx >> 4, c4 = idx & 15;
        float4 v = *(const float4*)(qb + (size_t)(q0 + r) * (3 * DM) + 4 * c4);
        int blk = c4 >> 2;
        int j0 = (2 * c4) & 7, j1 = (2 * c4 + 1) & 7;
        int s0 = r * BTS + blk * 8 + PPOS(j0);
        int s1 = r * BTS + blk * 8 + PPOS(j1);
        float hx = __bfloat162float(__float2bfloat16(v.x));
        float hy = __bfloat162float(__float2bfloat16(v.y));
        float hz = __bfloat162float(__float2bfloat16(v.z));
        float hw = __bfloat162float(__float2bfloat16(v.w));
        sqhi[s0] = pack_bf16(v.x, v.y);
        sqhi[s1] = pack_bf16(v.z, v.w);
        sqlo[s0] = pack_bf16(v.x - hx, v.y - hy);
        sqlo[s1] = pack_bf16(v.z - hz, v.w - hw);
    }

    float lsum[4] = {0.f, 0.f, 0.f, 0.f};      // [mt*2 + half]
    float o[2][8][4];
#pragma unroll
    for (int mt = 0; mt < 2; mt++)
#pragma unroll
        for (int nt = 0; nt < 8; nt++)
#pragma unroll
            for (int e = 0; e < 4; e++) o[mt][nt][e] = 0.f;

    float* wbase = w_out + ((size_t)(b * NH + h) * SL + q0) * SL;

    for (int kt = 0; kt <= ktv; kt++) {
        int k0 = kt * 64;
        __syncthreads();
        // ---- stage K hi/lo + V ----
#pragma unroll
        for (int i = 0; i < 4; i++) {
            int idx = tid + i * 256;
            int r = idx >> 4, c4 = idx & 15;
            float4 v = *(const float4*)(kb + (size_t)(k0 + r) * (3 * DM) + 4 * c4);
            int blk = c4 >> 2;
            int j0 = (2 * c4) & 7, j1 = (2 * c4 + 1) & 7;
            int s0 = r * BTS + blk * 8 + PPOS(j0);
            int s1 = r * BTS + blk * 8 + PPOS(j1);
            float hx = __bfloat162float(__float2bfloat16(v.x));
            float hy = __bfloat162float(__float2bfloat16(v.y));
            float hz = __bfloat162float(__float2bfloat16(v.z));
            float hw = __bfloat162float(__float2bfloat16(v.w));
            skhi[s0] = pack_bf16(v.x, v.y);
            skhi[s1] = pack_bf16(v.z, v.w);
            sklo[s0] = pack_bf16(v.x - hx, v.y - hy);
            sklo[s1] = pack_bf16(v.z - hz, v.w - hw);
            float4 vv = *(const float4*)(vb + (size_t)(k0 + r) * (3 * DM) + 4 * c4);
            int pr = P32(r);
            sv[(4 * c4 + 0) * 68 + pr] = to_tf32(vv.x);
            sv[(4 * c4 + 1) * 68 + pr] = to_tf32(vv.y);
            sv[(4 * c4 + 2) * 68 + pr] = to_tf32(vv.z);
            sv[(4 * c4 + 3) * 68 + pr] = to_tf32(vv.w);
        }
        __syncthreads();

        // ---- two 16-row subtiles sequentially (caps c[] at 32 regs) ----
#pragma unroll
        for (int mt = 0; mt < 2; mt++) {
            int wm = wq + mt * 16;

            float c[8][4];
#pragma unroll
            for (int nt = 0; nt < 8; nt++)
#pragma unroll
                for (int e = 0; e < 4; e++) c[nt][e] = 0.f;

#pragma unroll
            for (int kc = 0; kc < 4; kc++) {
                uint2 ah0 = *(uint2*)(sqhi + (wm + g) * BTS + kc * 8 + 2 * tg);
                uint2 ah1 = *(uint2*)(sqhi + (wm + g + 8) * BTS + kc * 8 + 2 * tg);
                uint2 al0 = *(uint2*)(sqlo + (wm + g) * BTS + kc * 8 + 2 * tg);
                uint2 al1 = *(uint2*)(sqlo + (wm + g + 8) * BTS + kc * 8 + 2 * tg);
#pragma unroll
                for (int nt = 0; nt < 8; nt++) {
                    uint2 bh = *(uint2*)(skhi + (nt * 8 + g) * BTS + kc * 8 + 2 * tg);
                    uint2 bl = *(uint2*)(sklo + (nt * 8 + g) * BTS + kc * 8 + 2 * tg);
                    mma_bf16(c[nt], ah0.x, ah1.x, ah0.y, ah1.y, bh.x, bh.y);
                    mma_bf16(c[nt], ah0.x, ah1.x, ah0.y, ah1.y, bl.x, bl.y);
                    mma_bf16(c[nt], al0.x, al1.x, al0.y, al1.y, bh.x, bh.y);
                }
            }

#pragma unroll
            for (int nt = 0; nt < 8; nt++) {
                float p[4];
#pragma unroll
                for (int e = 0; e < 4; e++) {
                    int col = k0 + nt * 8 + 2 * tg + (e & 1);
                    int row = q0 + wm + g + ((e >> 1) << 3);
                    p[e] = (col <= row) ? __expf(c[nt][e] * scale) : 0.f;
                    lsum[mt * 2 + (e >> 1)] += p[e];
                }
                int colb = nt * 8 + 2 * tg;
                *(float2*)(wbase + (size_t)(wm + g) * SL + k0 + colb) =
                    make_float2(p[0], p[1]);
                *(float2*)(wbase + (size_t)(wm + g + 8) * SL + k0 + colb) =
                    make_float2(p[2], p[3]);
                int pc0 = P32(colb), pc1 = P32(colb + 1);
                sp[(wm + g) * 68 + pc0]     = to_tf32(p[0]);
                sp[(wm + g) * 68 + pc1]     = to_tf32(p[1]);
                sp[(wm + g + 8) * 68 + pc0] = to_tf32(p[2]);
                sp[(wm + g + 8) * 68 + pc1] = to_tf32(p[3]);
            }
        }
        __syncwarp();

        // ---- o += P @ V (tf32), per subtile ----
#pragma unroll
        for (int mt = 0; mt < 2; mt++) {
            int wm = wq + mt * 16;
#pragma unroll
            for (int kc = 0; kc < 64; kc += 32) {
                float4 a0 = *(float4*)(&sp[(wm + g) * 68 + kc + 8 * tg]);
                float4 a1 = *(float4*)(&sp[(wm + g) * 68 + kc + 8 * tg + 4]);
                float4 a2 = *(float4*)(&sp[(wm + g + 8) * 68 + kc + 8 * tg]);
                float4 a3 = *(float4*)(&sp[(wm + g + 8) * 68 + kc + 8 * tg + 4]);
                float a[4][4] = {{a0.x, a2.x, a0.y, a2.y}, {a0.z, a2.z, a0.w, a2.w},
                                 {a1.x, a3.x, a1.y, a3.y}, {a1.z, a3.z, a1.w, a3.w}};
#pragma unroll
                for (int j = 0; j < 4; j++)
#pragma unroll
                    for (int nt = 0; nt < 8; nt++) {
                        float2 bv = *(float2*)(&sv[(nt * 8 + g) * 68 + kc + 8 * tg + 2 * j]);
                        mma_tf32(o[mt][nt], a[j][0], a[j][1], a[j][2], a[j][3],
                                 bv.x, bv.y);
                    }
            }
        }
    }

    // zero the never-touched upper region
    int zstart = (ktv + 1) * 64;
    float4 z = make_float4(0.f, 0.f, 0.f, 0.f);
    for (int r = warp; r < QB; r += 8)
        for (int cc = zstart + lane * 4; cc < SL; cc += 128)
            *(float4*)(wbase + (size_t)r * SL + cc) = z;

    // reduce l across tg lanes
#pragma unroll
    for (int i = 0; i < 4; i++) {
        lsum[i] += __shfl_xor_sync(0xffffffffu, lsum[i], 1);
        lsum[i] += __shfl_xor_sync(0xffffffffu, lsum[i], 2);
    }

    if (tg == 0) {
        size_t lb = (size_t)(b * NH + h) * SL + q0;
#pragma unroll
        for (int mt = 0; mt < 2; mt++) {
            l_out[lb + wq + mt * 16 + g]     = lsum[mt * 2];
            l_out[lb + wq + mt * 16 + g + 8] = lsum[mt * 2 + 1];
        }
    }

    // write o scaled by 1/l, tf32-pre-rounded
#pragma unroll
    for (int mt = 0; mt < 2; mt++) {
        float inv0 = 1.f / lsum[mt * 2];
        float inv1 = 1.f / lsum[mt * 2 + 1];
        int wm = wq + mt * 16;
#pragma unroll
        for (int nt = 0; nt < 8; nt++) {
            int cold = nt * 8 + 2 * tg;
            size_t r0o = (size_t)((size_t)b * SL + q0 + wm + g) * DM + h * HD + cold;
            size_t r1o = (size_t)((size_t)b * SL + q0 + wm + g + 8) * DM + h * HD + cold;
            *(float2*)(o_out + r0o) = make_float2(to_tf32(o[mt][nt][0] * inv0),
                                                  to_tf32(o[mt][nt][1] * inv0));
            *(float2*)(o_out + r1o) = make_float2(to_tf32(o[mt][nt][2] * inv1),
                                                  to_tf32(o[mt][nt][3] * inv1));
        }
    }
}

// ---------------------------------------------------------------------------
// Normalize w rows by 1/l — 4 rows per block, 64-thread slice per row.
// ---------------------------------------------------------------------------
__global__ __launch_bounds__(256) void norm_kernel(
    float* __restrict__ w, const float* __restrict__ l)
{
    int row = blockIdx.x * 4 + (threadIdx.x >> 6);
    int t = threadIdx.x & 63;
    int q = row & (SL - 1);
    float inv = 1.f / l[row];
    int ncols = ((q >> 6) + 1) << 6;
    float* wr = w + (size_t)row * SL;
    for (int c = t * 4; c < ncols; c += 256) {
        float4 v = *(float4*)(wr + c);
        v.x *= inv; v.y *= inv; v.z *= inv; v.w *= inv;
        *(float4*)(wr + c) = v;
    }
}

// ---------------------------------------------------------------------------
extern "C" void kernel_launch(void* const* d_in, const int* in_sizes, int n_in,
                              void* d_out, int out_size)
{
    const float* x      = (const float*)d_in[0];  // (2,2048,1024)
    const float* w_qkv  = (const float*)d_in[1];  // (1024,3072)
    const float* w_proj = (const float*)d_in[2];  // (1024,1024)
    float* out    = (float*)d_out;                 // (2,2048,1024)
    float* w_attn = out + (size_t)MR * DM;         // (2,16,2048,2048)

    float *qkvp, *op, *xr, *wT, *lp;
    cudaGetSymbolAddress((void**)&qkvp, g_qkv);
    cudaGetSymbolAddress((void**)&op,   g_o);
    cudaGetSymbolAddress((void**)&xr,   g_xr);
    cudaGetSymbolAddress((void**)&wT,   g_wT);
    cudaGetSymbolAddress((void**)&lp,   g_l);
    float* wprojT = wT + (size_t)3 * DM * DM;

    cudaFuncSetAttribute(mma_gemm2,
                         cudaFuncAttributeMaxDynamicSharedMemorySize, GEMM2_SMEM);
    cudaFuncSetAttribute(attn_sp,
                         cudaFuncAttributeMaxDynamicSharedMemorySize, ATTN_SMEM);

    // 0) prep: round x; round+transpose weights
    round_tf32_kernel<<<(MR * DM / 4 + 255) / 256, 256>>>(x, xr, MR * DM / 4);
    transpose_round32<<<dim3(3 * DM / 32, DM / 32), dim3(32, 8)>>>(w_qkv, wT, DM, 3 * DM);
    transpose_round32<<<dim3(DM / 32, DM / 32), dim3(32, 8)>>>(w_proj, wprojT, DM, DM);

    // 1) qkv = x @ w_qkv
    dim3 g1(3 * DM / 256, MR / 128);
    mma_gemm2<<<g1, 256, GEMM2_SMEM>>>(xr, wT, qkvp, MR, 3 * DM, DM);

    // 2) single-pass attention (q-block 256)
    dim3 g2(SL / QB, NH, BSZ);
    attn_sp<<<g2, 256, ATTN_SMEM>>>(qkvp, w_attn, op, lp);

    // 3) normalize w rows
    norm_kernel<<<BSZ * NH * SL / 4, 256>>>(w_attn, lp);

    // 4) out = o @ w_proj
    dim3 g3(DM / 256, MR / 128);
    mma_gemm2<<<g3, 256, GEMM2_SMEM>>>(op, wprojT, out, MR, DM, DM);
}

// round 15
// speedup vs baseline: 1.1402x; 1.1402x over previous
#include <cuda_runtime.h>
#include <cuda_bf16.h>
#include <math.h>
#include <stdint.h>

#define BSZ 2
#define SL  2048
#define DM  1024
#define NH  16
#define HD  64
#define MR  (BSZ * SL)   // 4096 rows

__device__ float g_qkv[(size_t)MR * 3 * DM];   // 48 MB
__device__ float g_o  [(size_t)MR * DM];       // 16 MB (tf32-rounded o)
__device__ float g_xr [(size_t)MR * DM];       // 16 MB (tf32-rounded x)
__device__ float g_wT [(size_t)3 * DM * DM + (size_t)DM * DM]; // rounded, transposed weights
__device__ float g_l  [(size_t)BSZ * NH * SL]; // softmax denominators
// prep outputs for attention (K split + V transposed only)
__device__ uint32_t g_khi[(size_t)MR * NH * 32];       // 8 MB
__device__ uint32_t g_klo[(size_t)MR * NH * 32];       // 8 MB
__device__ float    g_vt [(size_t)BSZ * NH * HD * SL]; // 16 MB, [bh][d][perm seq]

// ---------------------------------------------------------------------------
__device__ __forceinline__ float to_tf32(float x) {
    asm("cvt.rna.tf32.f32 %0, %0;" : "+f"(x));
    return x;
}

__device__ __forceinline__ void mma_tf32(float c[4], const float a0, const float a1,
                                         const float a2, const float a3,
                                         const float b0, const float b1) {
    asm volatile(
        "mma.sync.aligned.m16n8k8.row.col.f32.tf32.tf32.f32 "
        "{%0,%1,%2,%3}, {%4,%5,%6,%7}, {%8,%9}, {%0,%1,%2,%3};"
        : "+f"(c[0]), "+f"(c[1]), "+f"(c[2]), "+f"(c[3])
        : "r"(__float_as_uint(a0)), "r"(__float_as_uint(a1)),
          "r"(__float_as_uint(a2)), "r"(__float_as_uint(a3)),
          "r"(__float_as_uint(b0)), "r"(__float_as_uint(b1)));
}

__device__ __forceinline__ void mma_bf16(float c[4], uint32_t a0, uint32_t a1,
                                         uint32_t a2, uint32_t a3,
                                         uint32_t b0, uint32_t b1) {
    asm volatile(
        "mma.sync.aligned.m16n8k16.row.col.f32.bf16.bf16.f32 "
        "{%0,%1,%2,%3}, {%4,%5,%6,%7}, {%8,%9}, {%0,%1,%2,%3};"
        : "+f"(c[0]), "+f"(c[1]), "+f"(c[2]), "+f"(c[3])
        : "r"(a0), "r"(a1), "r"(a2), "r"(a3), "r"(b0), "r"(b1));
}

__device__ __forceinline__ uint32_t pack_bf16(float a, float b) {
    __nv_bfloat162 t = __floats2bfloat162_rn(a, b);
    return *(uint32_t*)&t;
}

__device__ __forceinline__ uint32_t smem_u32(const void* p) {
    uint32_t a;
    asm("{ .reg .u64 t; cvta.to.shared.u64 t, %1; cvt.u32.u64 %0, t; }"
        : "=r"(a) : "l"(p));
    return a;
}

__device__ __forceinline__ void cp_async16(uint32_t dst, const void* src) {
    asm volatile("cp.async.ca.shared.global [%0], [%1], 16;"
                 :: "r"(dst), "l"(src));
}
__device__ __forceinline__ void cp_commit() {
    asm volatile("cp.async.commit_group;");
}
template <int N>
__device__ __forceinline__ void cp_wait() {
    asm volatile("cp.async.wait_group %0;" :: "n"(N));
}

#define P32(k)  ((((k) & 3) * 8) + (((k) >> 2) & 7) + ((k) & 32))
#define IP32(j) (((j) & 32) | (((j) & 7) << 2) | (((j) >> 3) & 3))
#define PPOS(j) ((((j) & 3) << 1) | (((j) & 7) >> 2))

// ---------------------------------------------------------------------------
// prep kernels
// ---------------------------------------------------------------------------
__global__ __launch_bounds__(256) void round_tf32_kernel(
    const float* __restrict__ src, float* __restrict__ dst, int n4)
{
    int i = blockIdx.x * 256 + threadIdx.x;
    if (i < n4) {
        float4 v = *(const float4*)(src + 4 * (size_t)i);
        v.x = to_tf32(v.x); v.y = to_tf32(v.y);
        v.z = to_tf32(v.z); v.w = to_tf32(v.w);
        *(float4*)(dst + 4 * (size_t)i) = v;
    }
}

__global__ __launch_bounds__(256) void transpose_round32(
    const float* __restrict__ src, float* __restrict__ dst, int R, int Cc)
{
    __shared__ float t[32][33];
    int r0 = blockIdx.y * 32, c0 = blockIdx.x * 32;
    int tx = threadIdx.x, ty = threadIdx.y;
#pragma unroll
    for (int j = 0; j < 32; j += 8)
        t[ty + j][tx] = to_tf32(src[(size_t)(r0 + ty + j) * Cc + c0 + tx]);
    __syncthreads();
#pragma unroll
    for (int j = 0; j < 32; j += 8)
        dst[(size_t)(c0 + ty + j) * R + r0 + tx] = t[tx][ty + j];
}

// Per (b, h, 64-seq tile): split K to bf16 hi/lo (permuted-pair layout),
// transpose V to [d][seq] (tf32-rounded, P32-permuted within each 64-block).
__global__ __launch_bounds__(256) void attn_prep(
    const float* __restrict__ qkv,
    uint32_t* __restrict__ khi, uint32_t* __restrict__ klo,
    float* __restrict__ vt)
{
    __shared__ float tv[64][65];
    int tid = threadIdx.x;
    int st = blockIdx.x * 64, h = blockIdx.y, b = blockIdx.z;

#pragma unroll
    for (int i = 0; i < 4; i++) {
        int idx = tid + i * 256;
        int r = idx >> 4, c4 = idx & 15;
        int s = st + r;
        const float* row = qkv + ((size_t)b * SL + s) * 3 * DM + h * HD;
        int blk = c4 >> 2;
        int s0 = blk * 8 + PPOS((2 * c4) & 7);
        int s1 = blk * 8 + PPOS((2 * c4 + 1) & 7);
        size_t base = ((size_t)((size_t)b * SL + s) * NH + h) * 32;

        // K split
        {
            float4 v = *(const float4*)(row + DM + 4 * c4);
            float hx = __bfloat162float(__float2bfloat16(v.x));
            float hy = __bfloat162float(__float2bfloat16(v.y));
            float hz = __bfloat162float(__float2bfloat16(v.z));
            float hw = __bfloat162float(__float2bfloat16(v.w));
            khi[base + s0] = pack_bf16(v.x, v.y);
            khi[base + s1] = pack_bf16(v.z, v.w);
            klo[base + s0] = pack_bf16(v.x - hx, v.y - hy);
            klo[base + s1] = pack_bf16(v.z - hz, v.w - hw);
        }
        // V into smem (tf32-rounded)
        {
            float4 v = *(const float4*)(row + 2 * DM + 4 * c4);
            tv[r][4 * c4 + 0] = to_tf32(v.x);
            tv[r][4 * c4 + 1] = to_tf32(v.y);
            tv[r][4 * c4 + 2] = to_tf32(v.z);
            tv[r][4 * c4 + 3] = to_tf32(v.w);
        }
    }
    __syncthreads();

    // write V transposed: vt[bh*64+d][st + j] = tv[IP32(j)][d]
#pragma unroll
    for (int i = 0; i < 4; i++) {
        int idx = tid + i * 256;
        int d = idx >> 4, c4 = idx & 15;
        float4 w;
        w.x = tv[IP32(4 * c4 + 0)][d];
        w.y = tv[IP32(4 * c4 + 1)][d];
        w.z = tv[IP32(4 * c4 + 2)][d];
        w.w = tv[IP32(4 * c4 + 3)][d];
        *(float4*)(vt + ((size_t)(b * NH + h) * HD + d) * SL + st + 4 * c4) = w;
    }
}

// ---------------------------------------------------------------------------
// TF32 GEMM v2 (unchanged from Round 9): C = A @ Bt^T, 128x256x32,
// 256 thr, warp tile 64x64, cp.async double-buffered.
// ---------------------------------------------------------------------------
#define GS_A (128 * 40)
#define GS_B (256 * 40)
#define GS_STAGE (GS_A + GS_B)
#define GEMM2_SMEM (2 * GS_STAGE * 4)

__global__ __launch_bounds__(256) void mma_gemm2(
    const float* __restrict__ A, const float* __restrict__ Bt,
    float* __restrict__ C, int M, int N, int K)
{
    extern __shared__ float gsm[];
    uint32_t sb = smem_u32(gsm);

    int tid  = threadIdx.x;
    int lane = tid & 31, warp = tid >> 5;
    int g = lane >> 2, tg = lane & 3;
    int wm = (warp & 1) * 64;
    int wn = (warp >> 1) * 64;
    int bm = blockIdx.y * 128, bn = blockIdx.x * 256;

    float c[4][8][4];
#pragma unroll
    for (int mt = 0; mt < 4; mt++)
#pragma unroll
        for (int nt = 0; nt < 8; nt++)
#pragma unroll
            for (int i = 0; i < 4; i++) c[mt][nt][i] = 0.f;

#define G2_ISSUE(S, K0)                                                        \
    {                                                                          \
        uint32_t abase = sb + (S) * GS_STAGE * 4;                              \
        uint32_t bbase = abase + GS_A * 4;                                     \
        _Pragma("unroll")                                                      \
        for (int i = 0; i < 4; i++) {                                          \
            int id = tid + 256 * i;                                            \
            int r = id >> 3, k4 = id & 7;                                      \
            cp_async16(abase + r * 160 + k4 * 16,                              \
                       A + (size_t)(bm + r) * K + (K0) + 4 * k4);              \
        }                                                                      \
        _Pragma("unroll")                                                      \
        for (int i = 0; i < 8; i++) {                                          \
            int id = tid + 256 * i;                                            \
            int n = id >> 3, k4 = id & 7;                                      \
            cp_async16(bbase + n * 160 + k4 * 16,                              \
                       Bt + (size_t)(bn + n) * K + (K0) + 4 * k4);             \
        }                                                                      \
        cp_commit();                                                           \
    }

    G2_ISSUE(0, 0);

    int nch = K / 32;
    for (int ch = 0; ch < nch; ch++) {
        int s = ch & 1;
        if (ch + 1 < nch) {
            G2_ISSUE(s ^ 1, (ch + 1) * 32);
            cp_wait<1>();
        } else {
            cp_wait<0>();
        }
        __syncthreads();

        const float* As = gsm + s * GS_STAGE;
        const float* Bs = As + GS_A;

#pragma unroll
        for (int j = 0; j < 4; j++) {
            int kc = 8 * j + 2 * tg;
            float2 af[4][2];
#pragma unroll
            for (int mt = 0; mt < 4; mt++) {
                int rl = wm + mt * 16 + g;
                af[mt][0] = *(const float2*)(As + rl * 40 + kc);
                af[mt][1] = *(const float2*)(As + (rl + 8) * 40 + kc);
            }
#pragma unroll
            for (int nt = 0; nt < 8; nt++) {
                float2 bf = *(const float2*)(Bs + (wn + nt * 8 + g) * 40 + kc);
#pragma unroll
                for (int mt = 0; mt < 4; mt++)
                    mma_tf32(c[mt][nt], af[mt][0].x, af[mt][1].x,
                             af[mt][0].y, af[mt][1].y, bf.x, bf.y);
            }
        }
        __syncthreads();
    }

#pragma unroll
    for (int mt = 0; mt < 4; mt++)
#pragma unroll
        for (int nt = 0; nt < 8; nt++) {
            int row = bm + wm + mt * 16 + g;
            int col = bn + wn + nt * 8 + 2 * tg;
            *(float2*)(C + (size_t)row * N + col) =
                make_float2(c[mt][nt][0], c[mt][nt][1]);
            *(float2*)(C + (size_t)(row + 8) * N + col) =
                make_float2(c[mt][nt][2], c[mt][nt][3]);
        }
}

// ---------------------------------------------------------------------------
// Single-pass causal attention v4: q-block 128 (R9 shape). Q staged in-kernel
// (read once); K hi/lo + V staged via double-buffered cp.async from prep
// arrays. QK = bf16 3-term split; PV = tf32. Unnormalized w + l.
// ---------------------------------------------------------------------------
// byte offsets in dynamic smem
#define QHI_OFF 0                        // 128 rows * 160B
#define QLO_OFF 20480
#define KHI_OFF 40960                    // 2 stages * 64 * 160B
#define KLO_OFF 61440
#define SV_OFF  81920                    // 2 stages * 64 * 272B
#define SP_OFF  116736                   // 128 * 272B
#define ATTN_SMEM 151552
#define BTS 40                           // q/k row stride in u32

__global__ __launch_bounds__(256) void attn_sp4(
    const float* __restrict__ qkv,
    const uint32_t* __restrict__ khiG, const uint32_t* __restrict__ kloG,
    const float* __restrict__ vtG,
    float* __restrict__ w_out, float* __restrict__ o_out,
    float* __restrict__ l_out)
{
    extern __shared__ char smc[];
    uint32_t sb = smem_u32(smc);
    uint32_t* sqhi = (uint32_t*)(smc + QHI_OFF);
    uint32_t* sqlo = (uint32_t*)(smc + QLO_OFF);
    float*    sp   = (float*)(smc + SP_OFF);

    int tid  = threadIdx.x;
    int lane = tid & 31, warp = tid >> 5;
    int g = lane >> 2, tg = lane & 3;
    int wm = warp * 16;
    int qt = (gridDim.x - 1) - blockIdx.x;     // heavy-first
    int h = blockIdx.y, b = blockIdx.z;
    int q0 = qt * 128;
    int ktv = 2 * qt + 1;
    const float scale = 0.125f;

    const float* qb = qkv + (size_t)b * SL * 3 * DM + (size_t)h * HD;

#define A4_ISSUE_KV(S, KT)                                                     \
    {                                                                          \
        int k0_ = (KT) * 64;                                                   \
        _Pragma("unroll")                                                      \
        for (int i = 0; i < 2; i++) {                                          \
            int idx = tid + i * 256;      /* 0..511 */                         \
            int r = idx >> 3, c = idx & 7;                                     \
            size_t src = ((size_t)((size_t)b * SL + k0_ + r) * NH + h) * 32 + 4 * c; \
            cp_async16(sb + KHI_OFF + (S) * 10240 + r * 160 + c * 16, khiG + src); \
            cp_async16(sb + KLO_OFF + (S) * 10240 + r * 160 + c * 16, kloG + src); \
        }                                                                      \
        _Pragma("unroll")                                                      \
        for (int i = 0; i < 4; i++) {                                          \
            int idx = tid + i * 256;      /* 0..1023 */                        \
            int d = idx >> 4, c = idx & 15;                                    \
            size_t src = ((size_t)(b * NH + h) * HD + d) * SL + k0_ + 4 * c;   \
            cp_async16(sb + SV_OFF + (S) * 17408 + d * 272 + c * 16, vtG + src); \
        }                                                                      \
        cp_commit();                                                           \
    }

    // issue first K/V tile, then stage Q in-kernel (overlaps the cp.async)
    A4_ISSUE_KV(0, 0);

#pragma unroll
    for (int i = 0; i < 8; i++) {
        int idx = tid + i * 256;
        int r = idx >> 4, c4 = idx & 15;
        float4 v = *(const float4*)(qb + (size_t)(q0 + r) * (3 * DM) + 4 * c4);
        int blk = c4 >> 2;
        int s0 = r * BTS + blk * 8 + PPOS((2 * c4) & 7);
        int s1 = r * BTS + blk * 8 + PPOS((2 * c4 + 1) & 7);
        float hx = __bfloat162float(__float2bfloat16(v.x));
        float hy = __bfloat162float(__float2bfloat16(v.y));
        float hz = __bfloat162float(__float2bfloat16(v.z));
        float hw = __bfloat162float(__float2bfloat16(v.w));
        sqhi[s0] = pack_bf16(v.x, v.y);
        sqhi[s1] = pack_bf16(v.z, v.w);
        sqlo[s0] = pack_bf16(v.x - hx, v.y - hy);
        sqlo[s1] = pack_bf16(v.z - hz, v.w - hw);
    }

    float lsum[2] = {0.f, 0.f};
    float o[8][4];
#pragma unroll
    for (int nt = 0; nt < 8; nt++)
#pragma unroll
        for (int e = 0; e < 4; e++) o[nt][e] = 0.f;

    float* wbase = w_out + ((size_t)(b * NH + h) * SL + q0) * SL;

    for (int kt = 0; kt <= ktv; kt++) {
        int s = kt & 1;
        if (kt < ktv) {
            __syncthreads();               // reads of buffer s^1 done; Q visible
            A4_ISSUE_KV(s ^ 1, kt + 1);
            cp_wait<1>();
        } else {
            cp_wait<0>();
        }
        __syncthreads();                   // staged data visible to all

        uint32_t* skhi = (uint32_t*)(smc + KHI_OFF + s * 10240);
        uint32_t* sklo = (uint32_t*)(smc + KLO_OFF + s * 10240);
        float*    sv   = (float*)(smc + SV_OFF + s * 17408);
        int k0 = kt * 64;

        float c[8][4];
#pragma unroll
        for (int nt = 0; nt < 8; nt++)
#pragma unroll
            for (int e = 0; e < 4; e++) c[nt][e] = 0.f;

#pragma unroll
        for (int kc = 0; kc < 4; kc++) {
            uint2 ah0 = *(uint2*)(sqhi + (wm + g) * BTS + kc * 8 + 2 * tg);
            uint2 ah1 = *(uint2*)(sqhi + (wm + g + 8) * BTS + kc * 8 + 2 * tg);
            uint2 al0 = *(uint2*)(sqlo + (wm + g) * BTS + kc * 8 + 2 * tg);
            uint2 al1 = *(uint2*)(sqlo + (wm + g + 8) * BTS + kc * 8 + 2 * tg);
#pragma unroll
            for (int nt = 0; nt < 8; nt++) {
                uint2 bh = *(uint2*)(skhi + (nt * 8 + g) * BTS + kc * 8 + 2 * tg);
                uint2 bl = *(uint2*)(sklo + (nt * 8 + g) * BTS + kc * 8 + 2 * tg);
                mma_bf16(c[nt], ah0.x, ah1.x, ah0.y, ah1.y, bh.x, bh.y);
                mma_bf16(c[nt], ah0.x, ah1.x, ah0.y, ah1.y, bl.x, bl.y);
                mma_bf16(c[nt], al0.x, al1.x, al0.y, al1.y, bh.x, bh.y);
            }
        }

#pragma unroll
        for (int nt = 0; nt < 8; nt++) {
            float p[4];
#pragma unroll
            for (int e = 0; e < 4; e++) {
                int col = k0 + nt * 8 + 2 * tg + (e & 1);
                int row = q0 + wm + g + ((e >> 1) << 3);
                p[e] = (col <= row) ? __expf(c[nt][e] * scale) : 0.f;
                lsum[e >> 1] += p[e];
            }
            int colb = nt * 8 + 2 * tg;
            *(float2*)(wbase + (size_t)(wm + g) * SL + k0 + colb) =
                make_float2(p[0], p[1]);
            *(float2*)(wbase + (size_t)(wm + g + 8) * SL + k0 + colb) =
                make_float2(p[2], p[3]);
            int pc0 = P32(colb), pc1 = P32(colb + 1);
            sp[(wm + g) * 68 + pc0]     = to_tf32(p[0]);
            sp[(wm + g) * 68 + pc1]     = to_tf32(p[1]);
            sp[(wm + g + 8) * 68 + pc0] = to_tf32(p[2]);
            sp[(wm + g + 8) * 68 + pc1] = to_tf32(p[3]);
        }
        __syncwarp();

#pragma unroll
        for (int kc = 0; kc < 64; kc += 32) {
            float4 a0 = *(float4*)(&sp[(wm + g) * 68 + kc + 8 * tg]);
            float4 a1 = *(float4*)(&sp[(wm + g) * 68 + kc + 8 * tg + 4]);
            float4 a2 = *(float4*)(&sp[(wm + g + 8) * 68 + kc + 8 * tg]);
            float4 a3 = *(float4*)(&sp[(wm + g + 8) * 68 + kc + 8 * tg + 4]);
            float a[4][4] = {{a0.x, a2.x, a0.y, a2.y}, {a0.z, a2.z, a0.w, a2.w},
                             {a1.x, a3.x, a1.y, a3.y}, {a1.z, a3.z, a1.w, a3.w}};
#pragma unroll
            for (int j = 0; j < 4; j++)
#pragma unroll
                for (int nt = 0; nt < 8; nt++) {
                    float2 bv = *(float2*)(&sv[(nt * 8 + g) * 68 + kc + 8 * tg + 2 * j]);
                    mma_tf32(o[nt], a[j][0], a[j][1], a[j][2], a[j][3], bv.x, bv.y);
                }
        }
    }

    // zero the never-touched upper region
    int zstart = (ktv + 1) * 64;
    float4 z = make_float4(0.f, 0.f, 0.f, 0.f);
    for (int r = warp; r < 128; r += 8)
        for (int cc = zstart + lane * 4; cc < SL; cc += 128)
            *(float4*)(wbase + (size_t)r * SL + cc) = z;

    lsum[0] += __shfl_xor_sync(0xffffffffu, lsum[0], 1);
    lsum[0] += __shfl_xor_sync(0xffffffffu, lsum[0], 2);
    lsum[1] += __shfl_xor_sync(0xffffffffu, lsum[1], 1);
    lsum[1] += __shfl_xor_sync(0xffffffffu, lsum[1], 2);
    float inv_l[2] = {1.f / lsum[0], 1.f / lsum[1]};

    if (tg == 0) {
        size_t lb = (size_t)(b * NH + h) * SL + q0;
        l_out[lb + wm + g]     = lsum[0];
        l_out[lb + wm + g + 8] = lsum[1];
    }

    // write o scaled by 1/l, tf32-pre-rounded (proj GEMM reads it raw)
#pragma unroll
    for (int nt = 0; nt < 8; nt++) {
        int cold = nt * 8 + 2 * tg;
        size_t r0o = (size_t)((size_t)b * SL + q0 + wm + g) * DM + h * HD + cold;
        size_t r1o = (size_t)((size_t)b * SL + q0 + wm + g + 8) * DM + h * HD + cold;
        *(float2*)(o_out + r0o) = make_float2(to_tf32(o[nt][0] * inv_l[0]),
                                              to_tf32(o[nt][1] * inv_l[0]));
        *(float2*)(o_out + r1o) = make_float2(to_tf32(o[nt][2] * inv_l[1]),
                                              to_tf32(o[nt][3] * inv_l[1]));
    }
}

// ---------------------------------------------------------------------------
__global__ __launch_bounds__(128) void norm_kernel(
    float* __restrict__ w, const float* __restrict__ l)
{
    int row = blockIdx.x;
    int q = row & (SL - 1);
    float inv = 1.f / l[row];
    int ncols = ((q >> 6) + 1) << 6;
    float* wr = w + (size_t)row * SL;
    for (int c = threadIdx.x * 4; c < ncols; c += blockDim.x * 4) {
        float4 v = *(float4*)(wr + c);
        v.x *= inv; v.y *= inv; v.z *= inv; v.w *= inv;
        *(float4*)(wr + c) = v;
    }
}

// ---------------------------------------------------------------------------
extern "C" void kernel_launch(void* const* d_in, const int* in_sizes, int n_in,
                              void* d_out, int out_size)
{
    const float* x      = (const float*)d_in[0];  // (2,2048,1024)
    const float* w_qkv  = (const float*)d_in[1];  // (1024,3072)
    const float* w_proj = (const float*)d_in[2];  // (1024,1024)
    float* out    = (float*)d_out;                 // (2,2048,1024)
    float* w_attn = out + (size_t)MR * DM;         // (2,16,2048,2048)

    float *qkvp, *op, *xr, *wT, *lp, *vt;
    uint32_t *khi, *klo;
    cudaGetSymbolAddress((void**)&qkvp, g_qkv);
    cudaGetSymbolAddress((void**)&op,   g_o);
    cudaGetSymbolAddress((void**)&xr,   g_xr);
    cudaGetSymbolAddress((void**)&wT,   g_wT);
    cudaGetSymbolAddress((void**)&lp,   g_l);
    cudaGetSymbolAddress((void**)&khi,  g_khi);
    cudaGetSymbolAddress((void**)&klo,  g_klo);
    cudaGetSymbolAddress((void**)&vt,   g_vt);
    float* wprojT = wT + (size_t)3 * DM * DM;

    cudaFuncSetAttribute(mma_gemm2,
                         cudaFuncAttributeMaxDynamicSharedMemorySize, GEMM2_SMEM);
    cudaFuncSetAttribute(attn_sp4,
                         cudaFuncAttributeMaxDynamicSharedMemorySize, ATTN_SMEM);

    // 0) prep: round x; round+transpose weights
    round_tf32_kernel<<<(MR * DM / 4 + 255) / 256, 256>>>(x, xr, MR * DM / 4);
    transpose_round32<<<dim3(3 * DM / 32, DM / 32), dim3(32, 8)>>>(w_qkv, wT, DM, 3 * DM);
    transpose_round32<<<dim3(DM / 32, DM / 32), dim3(32, 8)>>>(w_proj, wprojT, DM, DM);

    // 1) qkv = x @ w_qkv
    dim3 g1(3 * DM / 256, MR / 128);
    mma_gemm2<<<g1, 256, GEMM2_SMEM>>>(xr, wT, qkvp, MR, 3 * DM, DM);

    // 1.5) attention prep: split K, transpose V
    attn_prep<<<dim3(SL / 64, NH, BSZ), 256>>>(qkvp, khi, klo, vt);

    // 2) single-pass attention (q-block 128, cp.async K/V staging)
    dim3 g2(SL / 128, NH, BSZ);
    attn_sp4<<<g2, 256, ATTN_SMEM>>>(qkvp, khi, klo, vt, w_attn, op, lp);

    // 3) normalize w rows
    norm_kernel<<<BSZ * NH * SL, 128>>>(w_attn, lp);

    // 4) out = o @ w_proj
    dim3 g3(DM / 256, MR / 128);
    mma_gemm2<<<g3, 256, GEMM2_SMEM>>>(op, wprojT, out, MR, DM, DM);
}

// round 16
// speedup vs baseline: 1.1438x; 1.0032x over previous
#include <cuda_runtime.h>
#include <cuda_bf16.h>
#include <math.h>
#include <stdint.h>

#define BSZ 2
#define SL  2048
#define DM  1024
#define NH  16
#define HD  64
#define MR  (BSZ * SL)   // 4096 rows

__device__ float g_qkv[(size_t)MR * 3 * DM];   // 48 MB
__device__ float g_o  [(size_t)MR * DM];       // 16 MB (tf32-rounded o)
__device__ float g_xr [(size_t)MR * DM];       // 16 MB (tf32-rounded x)
__device__ float g_wT [(size_t)3 * DM * DM + (size_t)DM * DM]; // rounded, transposed weights
__device__ float g_l  [(size_t)BSZ * NH * SL]; // softmax denominators
// prep outputs for attention (K split + V transposed only)
__device__ uint32_t g_khi[(size_t)MR * NH * 32];       // 8 MB
__device__ uint32_t g_klo[(size_t)MR * NH * 32];       // 8 MB
__device__ float    g_vt [(size_t)BSZ * NH * HD * SL]; // 16 MB, [bh][d][perm seq]

// ---------------------------------------------------------------------------
__device__ __forceinline__ float to_tf32(float x) {
    asm("cvt.rna.tf32.f32 %0, %0;" : "+f"(x));
    return x;
}

__device__ __forceinline__ void mma_tf32(float c[4], const float a0, const float a1,
                                         const float a2, const float a3,
                                         const float b0, const float b1) {
    asm volatile(
        "mma.sync.aligned.m16n8k8.row.col.f32.tf32.tf32.f32 "
        "{%0,%1,%2,%3}, {%4,%5,%6,%7}, {%8,%9}, {%0,%1,%2,%3};"
        : "+f"(c[0]), "+f"(c[1]), "+f"(c[2]), "+f"(c[3])
        : "r"(__float_as_uint(a0)), "r"(__float_as_uint(a1)),
          "r"(__float_as_uint(a2)), "r"(__float_as_uint(a3)),
          "r"(__float_as_uint(b0)), "r"(__float_as_uint(b1)));
}

__device__ __forceinline__ void mma_bf16(float c[4], uint32_t a0, uint32_t a1,
                                         uint32_t a2, uint32_t a3,
                                         uint32_t b0, uint32_t b1) {
    asm volatile(
        "mma.sync.aligned.m16n8k16.row.col.f32.bf16.bf16.f32 "
        "{%0,%1,%2,%3}, {%4,%5,%6,%7}, {%8,%9}, {%0,%1,%2,%3};"
        : "+f"(c[0]), "+f"(c[1]), "+f"(c[2]), "+f"(c[3])
        : "r"(a0), "r"(a1), "r"(a2), "r"(a3), "r"(b0), "r"(b1));
}

__device__ __forceinline__ uint32_t pack_bf16(float a, float b) {
    __nv_bfloat162 t = __floats2bfloat162_rn(a, b);
    return *(uint32_t*)&t;
}

__device__ __forceinline__ uint32_t smem_u32(const void* p) {
    uint32_t a;
    asm("{ .reg .u64 t; cvta.to.shared.u64 t, %1; cvt.u32.u64 %0, t; }"
        : "=r"(a) : "l"(p));
    return a;
}

__device__ __forceinline__ void cp_async16(uint32_t dst, const void* src) {
    asm volatile("cp.async.ca.shared.global [%0], [%1], 16;"
                 :: "r"(dst), "l"(src));
}
__device__ __forceinline__ void cp_commit() {
    asm volatile("cp.async.commit_group;");
}
template <int N>
__device__ __forceinline__ void cp_wait() {
    asm volatile("cp.async.wait_group %0;" :: "n"(N));
}

#define P32(k)  ((((k) & 3) * 8) + (((k) >> 2) & 7) + ((k) & 32))
#define IP32(j) (((j) & 32) | (((j) & 7) << 2) | (((j) >> 3) & 3))
#define PPOS(j) ((((j) & 3) << 1) | (((j) & 7) >> 2))

// ---------------------------------------------------------------------------
// prep kernels
// ---------------------------------------------------------------------------
__global__ __launch_bounds__(256) void round_tf32_kernel(
    const float* __restrict__ src, float* __restrict__ dst, int n4)
{
    int i = blockIdx.x * 256 + threadIdx.x;
    if (i < n4) {
        float4 v = *(const float4*)(src + 4 * (size_t)i);
        v.x = to_tf32(v.x); v.y = to_tf32(v.y);
        v.z = to_tf32(v.z); v.w = to_tf32(v.w);
        *(float4*)(dst + 4 * (size_t)i) = v;
    }
}

__global__ __launch_bounds__(256) void transpose_round32(
    const float* __restrict__ src, float* __restrict__ dst, int R, int Cc)
{
    __shared__ float t[32][33];
    int r0 = blockIdx.y * 32, c0 = blockIdx.x * 32;
    int tx = threadIdx.x, ty = threadIdx.y;
#pragma unroll
    for (int j = 0; j < 32; j += 8)
        t[ty + j][tx] = to_tf32(src[(size_t)(r0 + ty + j) * Cc + c0 + tx]);
    __syncthreads();
#pragma unroll
    for (int j = 0; j < 32; j += 8)
        dst[(size_t)(c0 + ty + j) * R + r0 + tx] = t[tx][ty + j];
}

// Per (b, h, 64-seq tile): split K to bf16 hi/lo (permuted-pair layout),
// transpose V to [d][seq] (tf32-rounded, P32-permuted within each 64-block).
__global__ __launch_bounds__(256) void attn_prep(
    const float* __restrict__ qkv,
    uint32_t* __restrict__ khi, uint32_t* __restrict__ klo,
    float* __restrict__ vt)
{
    __shared__ float tv[64][65];
    int tid = threadIdx.x;
    int st = blockIdx.x * 64, h = blockIdx.y, b = blockIdx.z;

#pragma unroll
    for (int i = 0; i < 4; i++) {
        int idx = tid + i * 256;
        int r = idx >> 4, c4 = idx & 15;
        int s = st + r;
        const float* row = qkv + ((size_t)b * SL + s) * 3 * DM + h * HD;
        int blk = c4 >> 2;
        int s0 = blk * 8 + PPOS((2 * c4) & 7);
        int s1 = blk * 8 + PPOS((2 * c4 + 1) & 7);
        size_t base = ((size_t)((size_t)b * SL + s) * NH + h) * 32;

        // K split
        {
            float4 v = *(const float4*)(row + DM + 4 * c4);
            float hx = __bfloat162float(__float2bfloat16(v.x));
            float hy = __bfloat162float(__float2bfloat16(v.y));
            float hz = __bfloat162float(__float2bfloat16(v.z));
            float hw = __bfloat162float(__float2bfloat16(v.w));
            khi[base + s0] = pack_bf16(v.x, v.y);
            khi[base + s1] = pack_bf16(v.z, v.w);
            klo[base + s0] = pack_bf16(v.x - hx, v.y - hy);
            klo[base + s1] = pack_bf16(v.z - hz, v.w - hw);
        }
        // V into smem (tf32-rounded)
        {
            float4 v = *(const float4*)(row + 2 * DM + 4 * c4);
            tv[r][4 * c4 + 0] = to_tf32(v.x);
            tv[r][4 * c4 + 1] = to_tf32(v.y);
            tv[r][4 * c4 + 2] = to_tf32(v.z);
            tv[r][4 * c4 + 3] = to_tf32(v.w);
        }
    }
    __syncthreads();

    // write V transposed: vt[bh*64+d][st + j] = tv[IP32(j)][d]
#pragma unroll
    for (int i = 0; i < 4; i++) {
        int idx = tid + i * 256;
        int d = idx >> 4, c4 = idx & 15;
        float4 w;
        w.x = tv[IP32(4 * c4 + 0)][d];
        w.y = tv[IP32(4 * c4 + 1)][d];
        w.z = tv[IP32(4 * c4 + 2)][d];
        w.w = tv[IP32(4 * c4 + 3)][d];
        *(float4*)(vt + ((size_t)(b * NH + h) * HD + d) * SL + st + 4 * c4) = w;
    }
}

// ---------------------------------------------------------------------------
// TF32 GEMM v3: C = A @ Bt^T, 128x256x32, 256 thr, warp tile 64x64.
// 3-stage cp.async pipeline, ONE __syncthreads per chunk.
// ---------------------------------------------------------------------------
#define GS_A (128 * 40)
#define GS_B (256 * 40)
#define GS_STAGE (GS_A + GS_B)
#define GEMM2_SMEM (3 * GS_STAGE * 4)

__global__ __launch_bounds__(256) void mma_gemm2(
    const float* __restrict__ A, const float* __restrict__ Bt,
    float* __restrict__ C, int M, int N, int K)
{
    extern __shared__ float gsm[];
    uint32_t sb = smem_u32(gsm);

    int tid  = threadIdx.x;
    int lane = tid & 31, warp = tid >> 5;
    int g = lane >> 2, tg = lane & 3;
    int wm = (warp & 1) * 64;
    int wn = (warp >> 1) * 64;
    int bm = blockIdx.y * 128, bn = blockIdx.x * 256;

    float c[4][8][4];
#pragma unroll
    for (int mt = 0; mt < 4; mt++)
#pragma unroll
        for (int nt = 0; nt < 8; nt++)
#pragma unroll
            for (int i = 0; i < 4; i++) c[mt][nt][i] = 0.f;

#define G2_ISSUE(S, K0)                                                        \
    {                                                                          \
        uint32_t abase = sb + (uint32_t)(S) * (GS_STAGE * 4);                  \
        uint32_t bbase = abase + GS_A * 4;                                     \
        _Pragma("unroll")                                                      \
        for (int i = 0; i < 4; i++) {                                          \
            int id = tid + 256 * i;                                            \
            int r = id >> 3, k4 = id & 7;                                      \
            cp_async16(abase + r * 160 + k4 * 16,                              \
                       A + (size_t)(bm + r) * K + (K0) + 4 * k4);              \
        }                                                                      \
        _Pragma("unroll")                                                      \
        for (int i = 0; i < 8; i++) {                                          \
            int id = tid + 256 * i;                                            \
            int n = id >> 3, k4 = id & 7;                                      \
            cp_async16(bbase + n * 160 + k4 * 16,                              \
                       Bt + (size_t)(bn + n) * K + (K0) + 4 * k4);             \
        }                                                                      \
        cp_commit();                                                           \
    }

    G2_ISSUE(0, 0);
    G2_ISSUE(1, 32);

    int nch = K / 32;
    for (int ch = 0; ch < nch; ch++) {
        int s = ch % 3;
        cp_wait<1>();
        __syncthreads();               // stage s data visible; stage (ch+2)%3 free
        if (ch + 2 < nch) {
            int s2 = (ch + 2) % 3;
            G2_ISSUE(s2, (ch + 2) * 32);
        } else {
            cp_commit();               // empty group keeps wait<1> semantics
        }

        const float* As = gsm + s * GS_STAGE;
        const float* Bs = As + GS_A;

#pragma unroll
        for (int j = 0; j < 4; j++) {
            int kc = 8 * j + 2 * tg;
            float2 af[4][2];
#pragma unroll
            for (int mt = 0; mt < 4; mt++) {
                int rl = wm + mt * 16 + g;
                af[mt][0] = *(const float2*)(As + rl * 40 + kc);
                af[mt][1] = *(const float2*)(As + (rl + 8) * 40 + kc);
            }
#pragma unroll
            for (int nt = 0; nt < 8; nt++) {
                float2 bf = *(const float2*)(Bs + (wn + nt * 8 + g) * 40 + kc);
#pragma unroll
                for (int mt = 0; mt < 4; mt++)
                    mma_tf32(c[mt][nt], af[mt][0].x, af[mt][1].x,
                             af[mt][0].y, af[mt][1].y, bf.x, bf.y);
            }
        }
    }

#pragma unroll
    for (int mt = 0; mt < 4; mt++)
#pragma unroll
        for (int nt = 0; nt < 8; nt++) {
            int row = bm + wm + mt * 16 + g;
            int col = bn + wn + nt * 8 + 2 * tg;
            *(float2*)(C + (size_t)row * N + col) =
                make_float2(c[mt][nt][0], c[mt][nt][1]);
            *(float2*)(C + (size_t)(row + 8) * N + col) =
                make_float2(c[mt][nt][2], c[mt][nt][3]);
        }
}

// ---------------------------------------------------------------------------
// Single-pass causal attention v5: q-block 128, Q staged in-kernel,
// K hi/lo + V via 3-stage cp.async, ONE __syncthreads per tile.
// QK = bf16 3-term split; PV = tf32. Unnormalized w + l.
// ---------------------------------------------------------------------------
#define QHI_OFF 0                        // 128 rows * 160B
#define QLO_OFF 20480
#define KVB_OFF 40960                    // 3 stages * (khi 10240 + klo 10240 + sv 17408)
#define KVSTAGE 37888
#define SP_OFF  (40960 + 3 * KVSTAGE)    // 154624
#define ATTN_SMEM (SP_OFF + 128 * 68 * 4)  // 189440
#define BTS 40                           // q/k row stride in u32

__global__ __launch_bounds__(256) void attn_sp5(
    const float* __restrict__ qkv,
    const uint32_t* __restrict__ khiG, const uint32_t* __restrict__ kloG,
    const float* __restrict__ vtG,
    float* __restrict__ w_out, float* __restrict__ o_out,
    float* __restrict__ l_out)
{
    extern __shared__ char smc[];
    uint32_t sb = smem_u32(smc);
    uint32_t* sqhi = (uint32_t*)(smc + QHI_OFF);
    uint32_t* sqlo = (uint32_t*)(smc + QLO_OFF);
    float*    sp   = (float*)(smc + SP_OFF);

    int tid  = threadIdx.x;
    int lane = tid & 31, warp = tid >> 5;
    int g = lane >> 2, tg = lane & 3;
    int wm = warp * 16;
    int qt = (gridDim.x - 1) - blockIdx.x;     // heavy-first
    int h = blockIdx.y, b = blockIdx.z;
    int q0 = qt * 128;
    int ktv = 2 * qt + 1;
    const float scale = 0.125f;

    const float* qb = qkv + (size_t)b * SL * 3 * DM + (size_t)h * HD;

#define A5_ISSUE_KV(S, KT)                                                     \
    {                                                                          \
        int k0_ = (KT) * 64;                                                   \
        uint32_t kvb = sb + KVB_OFF + (uint32_t)(S) * KVSTAGE;                 \
        _Pragma("unroll")                                                      \
        for (int i = 0; i < 2; i++) {                                          \
            int idx = tid + i * 256;      /* 0..511 */                         \
            int r = idx >> 3, cc = idx & 7;                                    \
            size_t src = ((size_t)((size_t)b * SL + k0_ + r) * NH + h) * 32 + 4 * cc; \
            cp_async16(kvb + r * 160 + cc * 16, khiG + src);                   \
            cp_async16(kvb + 10240 + r * 160 + cc * 16, kloG + src);           \
        }                                                                      \
        _Pragma("unroll")                                                      \
        for (int i = 0; i < 4; i++) {                                          \
            int idx = tid + i * 256;      /* 0..1023 */                        \
            int d = idx >> 4, cc = idx & 15;                                   \
            size_t src = ((size_t)(b * NH + h) * HD + d) * SL + k0_ + 4 * cc;  \
            cp_async16(kvb + 20480 + d * 272 + cc * 16, vtG + src);            \
        }                                                                      \
        cp_commit();                                                           \
    }

    // issue first two K/V tiles, then stage Q (overlaps the cp.async)
    A5_ISSUE_KV(0, 0);
    if (ktv >= 1) { A5_ISSUE_KV(1, 1); } else { cp_commit(); }

#pragma unroll
    for (int i = 0; i < 8; i++) {
        int idx = tid + i * 256;
        int r = idx >> 4, c4 = idx & 15;
        float4 v = *(const float4*)(qb + (size_t)(q0 + r) * (3 * DM) + 4 * c4);
        int blk = c4 >> 2;
        int s0 = r * BTS + blk * 8 + PPOS((2 * c4) & 7);
        int s1 = r * BTS + blk * 8 + PPOS((2 * c4 + 1) & 7);
        float hx = __bfloat162float(__float2bfloat16(v.x));
        float hy = __bfloat162float(__float2bfloat16(v.y));
        float hz = __bfloat162float(__float2bfloat16(v.z));
        float hw = __bfloat162float(__float2bfloat16(v.w));
        sqhi[s0] = pack_bf16(v.x, v.y);
        sqhi[s1] = pack_bf16(v.z, v.w);
        sqlo[s0] = pack_bf16(v.x - hx, v.y - hy);
        sqlo[s1] = pack_bf16(v.z - hz, v.w - hw);
    }

    float lsum[2] = {0.f, 0.f};
    float o[8][4];
#pragma unroll
    for (int nt = 0; nt < 8; nt++)
#pragma unroll
        for (int e = 0; e < 4; e++) o[nt][e] = 0.f;

    float* wbase = w_out + ((size_t)(b * NH + h) * SL + q0) * SL;

    for (int kt = 0; kt <= ktv; kt++) {
        int s = kt % 3;
        cp_wait<1>();
        __syncthreads();               // tile kt data + Q visible; stage (kt+2)%3 free
        if (kt + 2 <= ktv) {
            int s2 = (kt + 2) % 3;
            A5_ISSUE_KV(s2, kt + 2);
        } else {
            cp_commit();
        }

        uint32_t* skhi = (uint32_t*)(smc + KVB_OFF + s * KVSTAGE);
        uint32_t* sklo = (uint32_t*)(smc + KVB_OFF + s * KVSTAGE + 10240);
        float*    sv   = (float*)(smc + KVB_OFF + s * KVSTAGE + 20480);
        int k0 = kt * 64;

        float c[8][4];
#pragma unroll
        for (int nt = 0; nt < 8; nt++)
#pragma unroll
            for (int e = 0; e < 4; e++) c[nt][e] = 0.f;

#pragma unroll
        for (int kc = 0; kc < 4; kc++) {
            uint2 ah0 = *(uint2*)(sqhi + (wm + g) * BTS + kc * 8 + 2 * tg);
            uint2 ah1 = *(uint2*)(sqhi + (wm + g + 8) * BTS + kc * 8 + 2 * tg);
            uint2 al0 = *(uint2*)(sqlo + (wm + g) * BTS + kc * 8 + 2 * tg);
            uint2 al1 = *(uint2*)(sqlo + (wm + g + 8) * BTS + kc * 8 + 2 * tg);
#pragma unroll
            for (int nt = 0; nt < 8; nt++) {
                uint2 bh = *(uint2*)(skhi + (nt * 8 + g) * BTS + kc * 8 + 2 * tg);
                uint2 bl = *(uint2*)(sklo + (nt * 8 + g) * BTS + kc * 8 + 2 * tg);
                mma_bf16(c[nt], ah0.x, ah1.x, ah0.y, ah1.y, bh.x, bh.y);
                mma_bf16(c[nt], ah0.x, ah1.x, ah0.y, ah1.y, bl.x, bl.y);
                mma_bf16(c[nt], al0.x, al1.x, al0.y, al1.y, bh.x, bh.y);
            }
        }

#pragma unroll
        for (int nt = 0; nt < 8; nt++) {
            float p[4];
#pragma unroll
            for (int e = 0; e < 4; e++) {
                int col = k0 + nt * 8 + 2 * tg + (e & 1);
                int row = q0 + wm + g + ((e >> 1) << 3);
                p[e] = (col <= row) ? __expf(c[nt][e] * scale) : 0.f;
                lsum[e >> 1] += p[e];
            }
            int colb = nt * 8 + 2 * tg;
            *(float2*)(wbase + (size_t)(wm + g) * SL + k0 + colb) =
                make_float2(p[0], p[1]);
            *(float2*)(wbase + (size_t)(wm + g + 8) * SL + k0 + colb) =
                make_float2(p[2], p[3]);
            int pc0 = P32(colb), pc1 = P32(colb + 1);
            sp[(wm + g) * 68 + pc0]     = to_tf32(p[0]);
            sp[(wm + g) * 68 + pc1]     = to_tf32(p[1]);
            sp[(wm + g + 8) * 68 + pc0] = to_tf32(p[2]);
            sp[(wm + g + 8) * 68 + pc1] = to_tf32(p[3]);
        }
        __syncwarp();

#pragma unroll
        for (int kc = 0; kc < 64; kc += 32) {
            float4 a0 = *(float4*)(&sp[(wm + g) * 68 + kc + 8 * tg]);
            float4 a1 = *(float4*)(&sp[(wm + g) * 68 + kc + 8 * tg + 4]);
            float4 a2 = *(float4*)(&sp[(wm + g + 8) * 68 + kc + 8 * tg]);
            float4 a3 = *(float4*)(&sp[(wm + g + 8) * 68 + kc + 8 * tg + 4]);
            float a[4][4] = {{a0.x, a2.x, a0.y, a2.y}, {a0.z, a2.z, a0.w, a2.w},
                             {a1.x, a3.x, a1.y, a3.y}, {a1.z, a3.z, a1.w, a3.w}};
#pragma unroll
            for (int j = 0; j < 4; j++)
#pragma unroll
                for (int nt = 0; nt < 8; nt++) {
                    float2 bv = *(float2*)(&sv[(nt * 8 + g) * 68 + kc + 8 * tg + 2 * j]);
                    mma_tf32(o[nt], a[j][0], a[j][1], a[j][2], a[j][3], bv.x, bv.y);
                }
        }
    }

    // zero the never-touched upper region
    int zstart = (ktv + 1) * 64;
    float4 z = make_float4(0.f, 0.f, 0.f, 0.f);
    for (int r = warp; r < 128; r += 8)
        for (int cc = zstart + lane * 4; cc < SL; cc += 128)
            *(float4*)(wbase + (size_t)r * SL + cc) = z;

    lsum[0] += __shfl_xor_sync(0xffffffffu, lsum[0], 1);
    lsum[0] += __shfl_xor_sync(0xffffffffu, lsum[0], 2);
    lsum[1] += __shfl_xor_sync(0xffffffffu, lsum[1], 1);
    lsum[1] += __shfl_xor_sync(0xffffffffu, lsum[1], 2);
    float inv_l[2] = {1.f / lsum[0], 1.f / lsum[1]};

    if (tg == 0) {
        size_t lb = (size_t)(b * NH + h) * SL + q0;
        l_out[lb + wm + g]     = lsum[0];
        l_out[lb + wm + g + 8] = lsum[1];
    }

    // write o scaled by 1/l, tf32-pre-rounded (proj GEMM reads it raw)
#pragma unroll
    for (int nt = 0; nt < 8; nt++) {
        int cold = nt * 8 + 2 * tg;
        size_t r0o = (size_t)((size_t)b * SL + q0 + wm + g) * DM + h * HD + cold;
        size_t r1o = (size_t)((size_t)b * SL + q0 + wm + g + 8) * DM + h * HD + cold;
        *(float2*)(o_out + r0o) = make_float2(to_tf32(o[nt][0] * inv_l[0]),
                                              to_tf32(o[nt][1] * inv_l[0]));
        *(float2*)(o_out + r1o) = make_float2(to_tf32(o[nt][2] * inv_l[1]),
                                              to_tf32(o[nt][3] * inv_l[1]));
    }
}

// ---------------------------------------------------------------------------
// Normalize w rows by 1/l — 2 rows per 256-thr block, streaming ld/st.
// ---------------------------------------------------------------------------
__global__ __launch_bounds__(256) void norm_kernel(
    float* __restrict__ w, const float* __restrict__ l)
{
    int row = blockIdx.x * 2 + (threadIdx.x >> 7);
    int t = threadIdx.x & 127;
    int q = row & (SL - 1);
    float inv = 1.f / l[row];
    int ncols = ((q >> 6) + 1) << 6;
    float* wr = w + (size_t)row * SL;
    for (int c = t * 4; c < ncols; c += 512) {
        float4 v = __ldcs((const float4*)(wr + c));
        v.x *= inv; v.y *= inv; v.z *= inv; v.w *= inv;
        __stcs((float4*)(wr + c), v);
    }
}

// ---------------------------------------------------------------------------
extern "C" void kernel_launch(void* const* d_in, const int* in_sizes, int n_in,
                              void* d_out, int out_size)
{
    const float* x      = (const float*)d_in[0];  // (2,2048,1024)
    const float* w_qkv  = (const float*)d_in[1];  // (1024,3072)
    const float* w_proj = (const float*)d_in[2];  // (1024,1024)
    float* out    = (float*)d_out;                 // (2,2048,1024)
    float* w_attn = out + (size_t)MR * DM;         // (2,16,2048,2048)

    float *qkvp, *op, *xr, *wT, *lp, *vt;
    uint32_t *khi, *klo;
    cudaGetSymbolAddress((void**)&qkvp, g_qkv);
    cudaGetSymbolAddress((void**)&op,   g_o);
    cudaGetSymbolAddress((void**)&xr,   g_xr);
    cudaGetSymbolAddress((void**)&wT,   g_wT);
    cudaGetSymbolAddress((void**)&lp,   g_l);
    cudaGetSymbolAddress((void**)&khi,  g_khi);
    cudaGetSymbolAddress((void**)&klo,  g_klo);
    cudaGetSymbolAddress((void**)&vt,   g_vt);
    float* wprojT = wT + (size_t)3 * DM * DM;

    cudaFuncSetAttribute(mma_gemm2,
                         cudaFuncAttributeMaxDynamicSharedMemorySize, GEMM2_SMEM);
    cudaFuncSetAttribute(attn_sp5,
                         cudaFuncAttributeMaxDynamicSharedMemorySize, ATTN_SMEM);

    // 0) prep: round x; round+transpose weights
    round_tf32_kernel<<<(MR * DM / 4 + 255) / 256, 256>>>(x, xr, MR * DM / 4);
    transpose_round32<<<dim3(3 * DM / 32, DM / 32), dim3(32, 8)>>>(w_qkv, wT, DM, 3 * DM);
    transpose_round32<<<dim3(DM / 32, DM / 32), dim3(32, 8)>>>(w_proj, wprojT, DM, DM);

    // 1) qkv = x @ w_qkv
    dim3 g1(3 * DM / 256, MR / 128);
    mma_gemm2<<<g1, 256, GEMM2_SMEM>>>(xr, wT, qkvp, MR, 3 * DM, DM);

    // 1.5) attention prep: split K, transpose V
    attn_prep<<<dim3(SL / 64, NH, BSZ), 256>>>(qkvp, khi, klo, vt);

    // 2) single-pass attention (q-block 128, 3-stage cp.async K/V staging)
    dim3 g2(SL / 128, NH, BSZ);
    attn_sp5<<<g2, 256, ATTN_SMEM>>>(qkvp, khi, klo, vt, w_attn, op, lp);

    // 3) normalize w rows
    norm_kernel<<<BSZ * NH * SL / 2, 256>>>(w_attn, lp);

    // 4) out = o @ w_proj
    dim3 g3(DM / 256, MR / 128);
    mma_gemm2<<<g3, 256, GEMM2_SMEM>>>(op, wprojT, out, MR, DM, DM);
}

// round 17
// speedup vs baseline: 1.1637x; 1.0174x over previous
#include <cuda_runtime.h>
#include <cuda_bf16.h>
#include <math.h>
#include <stdint.h>

#define BSZ 2
#define SL  2048
#define DM  1024
#define NH  16
#define HD  64
#define MR  (BSZ * SL)   // 4096 rows

__device__ float g_qkv[(size_t)MR * 3 * DM];   // 48 MB
__device__ float g_o  [(size_t)MR * DM];       // 16 MB (tf32-rounded o)
__device__ float g_xr [(size_t)MR * DM];       // 16 MB (tf32-rounded x)
__device__ float g_wT [(size_t)3 * DM * DM + (size_t)DM * DM]; // rounded, transposed weights
__device__ float g_l  [(size_t)BSZ * NH * SL]; // softmax denominators
// prep outputs for attention (K split + V transposed only)
__device__ uint32_t g_khi[(size_t)MR * NH * 32];       // 8 MB
__device__ uint32_t g_klo[(size_t)MR * NH * 32];       // 8 MB
__device__ float    g_vt [(size_t)BSZ * NH * HD * SL]; // 16 MB, [bh][d][perm seq]

// ---------------------------------------------------------------------------
__device__ __forceinline__ float to_tf32(float x) {
    asm("cvt.rna.tf32.f32 %0, %0;" : "+f"(x));
    return x;
}

__device__ __forceinline__ void mma_tf32(float c[4], const float a0, const float a1,
                                         const float a2, const float a3,
                                         const float b0, const float b1) {
    asm volatile(
        "mma.sync.aligned.m16n8k8.row.col.f32.tf32.tf32.f32 "
        "{%0,%1,%2,%3}, {%4,%5,%6,%7}, {%8,%9}, {%0,%1,%2,%3};"
        : "+f"(c[0]), "+f"(c[1]), "+f"(c[2]), "+f"(c[3])
        : "r"(__float_as_uint(a0)), "r"(__float_as_uint(a1)),
          "r"(__float_as_uint(a2)), "r"(__float_as_uint(a3)),
          "r"(__float_as_uint(b0)), "r"(__float_as_uint(b1)));
}

__device__ __forceinline__ void mma_bf16(float c[4], uint32_t a0, uint32_t a1,
                                         uint32_t a2, uint32_t a3,
                                         uint32_t b0, uint32_t b1) {
    asm volatile(
        "mma.sync.aligned.m16n8k16.row.col.f32.bf16.bf16.f32 "
        "{%0,%1,%2,%3}, {%4,%5,%6,%7}, {%8,%9}, {%0,%1,%2,%3};"
        : "+f"(c[0]), "+f"(c[1]), "+f"(c[2]), "+f"(c[3])
        : "r"(a0), "r"(a1), "r"(a2), "r"(a3), "r"(b0), "r"(b1));
}

__device__ __forceinline__ uint32_t pack_bf16(float a, float b) {
    __nv_bfloat162 t = __floats2bfloat162_rn(a, b);
    return *(uint32_t*)&t;
}

__device__ __forceinline__ uint32_t smem_u32(const void* p) {
    uint32_t a;
    asm("{ .reg .u64 t; cvta.to.shared.u64 t, %1; cvt.u32.u64 %0, t; }"
        : "=r"(a) : "l"(p));
    return a;
}

__device__ __forceinline__ void cp_async16(uint32_t dst, const void* src) {
    asm volatile("cp.async.ca.shared.global [%0], [%1], 16;"
                 :: "r"(dst), "l"(src));
}
__device__ __forceinline__ void cp_commit() {
    asm volatile("cp.async.commit_group;");
}
template <int N>
__device__ __forceinline__ void cp_wait() {
    asm volatile("cp.async.wait_group %0;" :: "n"(N));
}

__device__ __forceinline__ void stcs2(float* p, float a, float b) {
    __stcs((float2*)p, make_float2(a, b));
}

#define P32(k)  ((((k) & 3) * 8) + (((k) >> 2) & 7) + ((k) & 32))
#define IP32(j) (((j) & 32) | (((j) & 7) << 2) | (((j) >> 3) & 3))
#define PPOS(j) ((((j) & 3) << 1) | (((j) & 7) >> 2))

// ---------------------------------------------------------------------------
// prep kernels
// ---------------------------------------------------------------------------
__global__ __launch_bounds__(256) void round_tf32_kernel(
    const float* __restrict__ src, float* __restrict__ dst, int n4)
{
    int i = blockIdx.x * 256 + threadIdx.x;
    if (i < n4) {
        float4 v = *(const float4*)(src + 4 * (size_t)i);
        v.x = to_tf32(v.x); v.y = to_tf32(v.y);
        v.z = to_tf32(v.z); v.w = to_tf32(v.w);
        *(float4*)(dst + 4 * (size_t)i) = v;
    }
}

__global__ __launch_bounds__(256) void transpose_round32(
    const float* __restrict__ src, float* __restrict__ dst, int R, int Cc)
{
    __shared__ float t[32][33];
    int r0 = blockIdx.y * 32, c0 = blockIdx.x * 32;
    int tx = threadIdx.x, ty = threadIdx.y;
#pragma unroll
    for (int j = 0; j < 32; j += 8)
        t[ty + j][tx] = to_tf32(src[(size_t)(r0 + ty + j) * Cc + c0 + tx]);
    __syncthreads();
#pragma unroll
    for (int j = 0; j < 32; j += 8)
        dst[(size_t)(c0 + ty + j) * R + r0 + tx] = t[tx][ty + j];
}

// Per (b, h, 64-seq tile): split K to bf16 hi/lo (permuted-pair layout),
// transpose V to [d][seq] (tf32-rounded, P32-permuted within each 64-block).
__global__ __launch_bounds__(256) void attn_prep(
    const float* __restrict__ qkv,
    uint32_t* __restrict__ khi, uint32_t* __restrict__ klo,
    float* __restrict__ vt)
{
    __shared__ float tv[64][65];
    int tid = threadIdx.x;
    int st = blockIdx.x * 64, h = blockIdx.y, b = blockIdx.z;

#pragma unroll
    for (int i = 0; i < 4; i++) {
        int idx = tid + i * 256;
        int r = idx >> 4, c4 = idx & 15;
        int s = st + r;
        const float* row = qkv + ((size_t)b * SL + s) * 3 * DM + h * HD;
        int blk = c4 >> 2;
        int s0 = blk * 8 + PPOS((2 * c4) & 7);
        int s1 = blk * 8 + PPOS((2 * c4 + 1) & 7);
        size_t base = ((size_t)((size_t)b * SL + s) * NH + h) * 32;

        // K split
        {
            float4 v = *(const float4*)(row + DM + 4 * c4);
            float hx = __bfloat162float(__float2bfloat16(v.x));
            float hy = __bfloat162float(__float2bfloat16(v.y));
            float hz = __bfloat162float(__float2bfloat16(v.z));
            float hw = __bfloat162float(__float2bfloat16(v.w));
            khi[base + s0] = pack_bf16(v.x, v.y);
            khi[base + s1] = pack_bf16(v.z, v.w);
            klo[base + s0] = pack_bf16(v.x - hx, v.y - hy);
            klo[base + s1] = pack_bf16(v.z - hz, v.w - hw);
        }
        // V into smem (tf32-rounded)
        {
            float4 v = *(const float4*)(row + 2 * DM + 4 * c4);
            tv[r][4 * c4 + 0] = to_tf32(v.x);
            tv[r][4 * c4 + 1] = to_tf32(v.y);
            tv[r][4 * c4 + 2] = to_tf32(v.z);
            tv[r][4 * c4 + 3] = to_tf32(v.w);
        }
    }
    __syncthreads();

    // write V transposed: vt[bh*64+d][st + j] = tv[IP32(j)][d]
#pragma unroll
    for (int i = 0; i < 4; i++) {
        int idx = tid + i * 256;
        int d = idx >> 4, c4 = idx & 15;
        float4 w;
        w.x = tv[IP32(4 * c4 + 0)][d];
        w.y = tv[IP32(4 * c4 + 1)][d];
        w.z = tv[IP32(4 * c4 + 2)][d];
        w.w = tv[IP32(4 * c4 + 3)][d];
        *(float4*)(vt + ((size_t)(b * NH + h) * HD + d) * SL + st + 4 * c4) = w;
    }
}

// ---------------------------------------------------------------------------
// TF32 GEMM v4: C = A @ Bt^T. CTA tile 128x128, 128 thr / 4 warps,
// warp tile 64x64, 2-stage cp.async, 80KB smem -> 2 CTAs per SM.
// ---------------------------------------------------------------------------
#define GS_A (128 * 40)
#define GS_B (128 * 40)
#define GS_STAGE (GS_A + GS_B)
#define GEMM2_SMEM (2 * GS_STAGE * 4)   // 81920 bytes

__global__ __launch_bounds__(128, 2) void mma_gemm2(
    const float* __restrict__ A, const float* __restrict__ Bt,
    float* __restrict__ C, int M, int N, int K)
{
    extern __shared__ float gsm[];
    uint32_t sb = smem_u32(gsm);

    int tid  = threadIdx.x;
    int lane = tid & 31, warp = tid >> 5;
    int g = lane >> 2, tg = lane & 3;
    int wm = (warp & 1) * 64;
    int wn = (warp >> 1) * 64;
    int bm = blockIdx.y * 128, bn = blockIdx.x * 128;

    float c[4][8][4];
#pragma unroll
    for (int mt = 0; mt < 4; mt++)
#pragma unroll
        for (int nt = 0; nt < 8; nt++)
#pragma unroll
            for (int i = 0; i < 4; i++) c[mt][nt][i] = 0.f;

#define G2_ISSUE(S, K0)                                                        \
    {                                                                          \
        uint32_t abase = sb + (uint32_t)(S) * (GS_STAGE * 4);                  \
        uint32_t bbase = abase + GS_A * 4;                                     \
        _Pragma("unroll")                                                      \
        for (int i = 0; i < 8; i++) {                                          \
            int id = tid + 128 * i;                                            \
            int r = id >> 3, k4 = id & 7;                                      \
            cp_async16(abase + r * 160 + k4 * 16,                              \
                       A + (size_t)(bm + r) * K + (K0) + 4 * k4);              \
            cp_async16(bbase + r * 160 + k4 * 16,                              \
                       Bt + (size_t)(bn + r) * K + (K0) + 4 * k4);             \
        }                                                                      \
        cp_commit();                                                           \
    }

    G2_ISSUE(0, 0);

    int nch = K / 32;
    for (int ch = 0; ch < nch; ch++) {
        int s = ch & 1;
        if (ch + 1 < nch) {
            G2_ISSUE(s ^ 1, (ch + 1) * 32);
            cp_wait<1>();
        } else {
            cp_wait<0>();
        }
        __syncthreads();

        const float* As = gsm + s * GS_STAGE;
        const float* Bs = As + GS_A;

#pragma unroll
        for (int j = 0; j < 4; j++) {
            int kc = 8 * j + 2 * tg;
            float2 af[4][2];
#pragma unroll
            for (int mt = 0; mt < 4; mt++) {
                int rl = wm + mt * 16 + g;
                af[mt][0] = *(const float2*)(As + rl * 40 + kc);
                af[mt][1] = *(const float2*)(As + (rl + 8) * 40 + kc);
            }
#pragma unroll
            for (int nt = 0; nt < 8; nt++) {
                float2 bf = *(const float2*)(Bs + (wn + nt * 8 + g) * 40 + kc);
#pragma unroll
                for (int mt = 0; mt < 4; mt++)
                    mma_tf32(c[mt][nt], af[mt][0].x, af[mt][1].x,
                             af[mt][0].y, af[mt][1].y, bf.x, bf.y);
            }
        }
        __syncthreads();
    }

#pragma unroll
    for (int mt = 0; mt < 4; mt++)
#pragma unroll
        for (int nt = 0; nt < 8; nt++) {
            int row = bm + wm + mt * 16 + g;
            int col = bn + wn + nt * 8 + 2 * tg;
            *(float2*)(C + (size_t)row * N + col) =
                make_float2(c[mt][nt][0], c[mt][nt][1]);
            *(float2*)(C + (size_t)(row + 8) * N + col) =
                make_float2(c[mt][nt][2], c[mt][nt][3]);
        }
}

// ---------------------------------------------------------------------------
// Single-pass causal attention v5 (unchanged compute; w writes use streaming
// stores): q-block 128, Q staged in-kernel, K hi/lo + V via 3-stage cp.async.
// ---------------------------------------------------------------------------
#define QHI_OFF 0                        // 128 rows * 160B
#define QLO_OFF 20480
#define KVB_OFF 40960                    // 3 stages * (khi 10240 + klo 10240 + sv 17408)
#define KVSTAGE 37888
#define SP_OFF  (40960 + 3 * KVSTAGE)    // 154624
#define ATTN_SMEM (SP_OFF + 128 * 68 * 4)  // 189440
#define BTS 40                           // q/k row stride in u32

__global__ __launch_bounds__(256) void attn_sp5(
    const float* __restrict__ qkv,
    const uint32_t* __restrict__ khiG, const uint32_t* __restrict__ kloG,
    const float* __restrict__ vtG,
    float* __restrict__ w_out, float* __restrict__ o_out,
    float* __restrict__ l_out)
{
    extern __shared__ char smc[];
    uint32_t sb = smem_u32(smc);
    uint32_t* sqhi = (uint32_t*)(smc + QHI_OFF);
    uint32_t* sqlo = (uint32_t*)(smc + QLO_OFF);
    float*    sp   = (float*)(smc + SP_OFF);

    int tid  = threadIdx.x;
    int lane = tid & 31, warp = tid >> 5;
    int g = lane >> 2, tg = lane & 3;
    int wm = warp * 16;
    int qt = (gridDim.x - 1) - blockIdx.x;     // heavy-first
    int h = blockIdx.y, b = blockIdx.z;
    int q0 = qt * 128;
    int ktv = 2 * qt + 1;
    const float scale = 0.125f;

    const float* qb = qkv + (size_t)b * SL * 3 * DM + (size_t)h * HD;

#define A5_ISSUE_KV(S, KT)                                                     \
    {                                                                          \
        int k0_ = (KT) * 64;                                                   \
        uint32_t kvb = sb + KVB_OFF + (uint32_t)(S) * KVSTAGE;                 \
        _Pragma("unroll")                                                      \
        for (int i = 0; i < 2; i++) {                                          \
            int idx = tid + i * 256;      /* 0..511 */                         \
            int r = idx >> 3, cc = idx & 7;                                    \
            size_t src = ((size_t)((size_t)b * SL + k0_ + r) * NH + h) * 32 + 4 * cc; \
            cp_async16(kvb + r * 160 + cc * 16, khiG + src);                   \
            cp_async16(kvb + 10240 + r * 160 + cc * 16, kloG + src);           \
        }                                                                      \
        _Pragma("unroll")                                                      \
        for (int i = 0; i < 4; i++) {                                          \
            int idx = tid + i * 256;      /* 0..1023 */                        \
            int d = idx >> 4, cc = idx & 15;                                   \
            size_t src = ((size_t)(b * NH + h) * HD + d) * SL + k0_ + 4 * cc;  \
            cp_async16(kvb + 20480 + d * 272 + cc * 16, vtG + src);            \
        }                                                                      \
        cp_commit();                                                           \
    }

    // issue first two K/V tiles, then stage Q (overlaps the cp.async)
    A5_ISSUE_KV(0, 0);
    if (ktv >= 1) { A5_ISSUE_KV(1, 1); } else { cp_commit(); }

#pragma unroll
    for (int i = 0; i < 8; i++) {
        int idx = tid + i * 256;
        int r = idx >> 4, c4 = idx & 15;
        float4 v = *(const float4*)(qb + (size_t)(q0 + r) * (3 * DM) + 4 * c4);
        int blk = c4 >> 2;
        int s0 = r * BTS + blk * 8 + PPOS((2 * c4) & 7);
        int s1 = r * BTS + blk * 8 + PPOS((2 * c4 + 1) & 7);
        float hx = __bfloat162float(__float2bfloat16(v.x));
        float hy = __bfloat162float(__float2bfloat16(v.y));
        float hz = __bfloat162float(__float2bfloat16(v.z));
        float hw = __bfloat162float(__float2bfloat16(v.w));
        sqhi[s0] = pack_bf16(v.x, v.y);
        sqhi[s1] = pack_bf16(v.z, v.w);
        sqlo[s0] = pack_bf16(v.x - hx, v.y - hy);
        sqlo[s1] = pack_bf16(v.z - hz, v.w - hw);
    }

    float lsum[2] = {0.f, 0.f};
    float o[8][4];
#pragma unroll
    for (int nt = 0; nt < 8; nt++)
#pragma unroll
        for (int e = 0; e < 4; e++) o[nt][e] = 0.f;

    float* wbase = w_out + ((size_t)(b * NH + h) * SL + q0) * SL;

    for (int kt = 0; kt <= ktv; kt++) {
        int s = kt % 3;
        cp_wait<1>();
        __syncthreads();               // tile kt data + Q visible; stage (kt+2)%3 free
        if (kt + 2 <= ktv) {
            int s2 = (kt + 2) % 3;
            A5_ISSUE_KV(s2, kt + 2);
        } else {
            cp_commit();
        }

        uint32_t* skhi = (uint32_t*)(smc + KVB_OFF + s * KVSTAGE);
        uint32_t* sklo = (uint32_t*)(smc + KVB_OFF + s * KVSTAGE + 10240);
        float*    sv   = (float*)(smc + KVB_OFF + s * KVSTAGE + 20480);
        int k0 = kt * 64;

        float c[8][4];
#pragma unroll
        for (int nt = 0; nt < 8; nt++)
#pragma unroll
            for (int e = 0; e < 4; e++) c[nt][e] = 0.f;

#pragma unroll
        for (int kc = 0; kc < 4; kc++) {
            uint2 ah0 = *(uint2*)(sqhi + (wm + g) * BTS + kc * 8 + 2 * tg);
            uint2 ah1 = *(uint2*)(sqhi + (wm + g + 8) * BTS + kc * 8 + 2 * tg);
            uint2 al0 = *(uint2*)(sqlo + (wm + g) * BTS + kc * 8 + 2 * tg);
            uint2 al1 = *(uint2*)(sqlo + (wm + g + 8) * BTS + kc * 8 + 2 * tg);
#pragma unroll
            for (int nt = 0; nt < 8; nt++) {
                uint2 bh = *(uint2*)(skhi + (nt * 8 + g) * BTS + kc * 8 + 2 * tg);
                uint2 bl = *(uint2*)(sklo + (nt * 8 + g) * BTS + kc * 8 + 2 * tg);
                mma_bf16(c[nt], ah0.x, ah1.x, ah0.y, ah1.y, bh.x, bh.y);
                mma_bf16(c[nt], ah0.x, ah1.x, ah0.y, ah1.y, bl.x, bl.y);
                mma_bf16(c[nt], al0.x, al1.x, al0.y, al1.y, bh.x, bh.y);
            }
        }

#pragma unroll
        for (int nt = 0; nt < 8; nt++) {
            float p[4];
#pragma unroll
            for (int e = 0; e < 4; e++) {
                int col = k0 + nt * 8 + 2 * tg + (e & 1);
                int row = q0 + wm + g + ((e >> 1) << 3);
                p[e] = (col <= row) ? __expf(c[nt][e] * scale) : 0.f;
                lsum[e >> 1] += p[e];
            }
            int colb = nt * 8 + 2 * tg;
            stcs2(wbase + (size_t)(wm + g) * SL + k0 + colb, p[0], p[1]);
            stcs2(wbase + (size_t)(wm + g + 8) * SL + k0 + colb, p[2], p[3]);
            int pc0 = P32(colb), pc1 = P32(colb + 1);
            sp[(wm + g) * 68 + pc0]     = to_tf32(p[0]);
            sp[(wm + g) * 68 + pc1]     = to_tf32(p[1]);
            sp[(wm + g + 8) * 68 + pc0] = to_tf32(p[2]);
            sp[(wm + g + 8) * 68 + pc1] = to_tf32(p[3]);
        }
        __syncwarp();

#pragma unroll
        for (int kc = 0; kc < 64; kc += 32) {
            float4 a0 = *(float4*)(&sp[(wm + g) * 68 + kc + 8 * tg]);
            float4 a1 = *(float4*)(&sp[(wm + g) * 68 + kc + 8 * tg + 4]);
            float4 a2 = *(float4*)(&sp[(wm + g + 8) * 68 + kc + 8 * tg]);
            float4 a3 = *(float4*)(&sp[(wm + g + 8) * 68 + kc + 8 * tg + 4]);
            float a[4][4] = {{a0.x, a2.x, a0.y, a2.y}, {a0.z, a2.z, a0.w, a2.w},
                             {a1.x, a3.x, a1.y, a3.y}, {a1.z, a3.z, a1.w, a3.w}};
#pragma unroll
            for (int j = 0; j < 4; j++)
#pragma unroll
                for (int nt = 0; nt < 8; nt++) {
                    float2 bv = *(float2*)(&sv[(nt * 8 + g) * 68 + kc + 8 * tg + 2 * j]);
                    mma_tf32(o[nt], a[j][0], a[j][1], a[j][2], a[j][3], bv.x, bv.y);
                }
        }
    }

    // zero the never-touched upper region (streaming stores)
    int zstart = (ktv + 1) * 64;
    for (int r = warp; r < 128; r += 8)
        for (int cc = zstart + lane * 4; cc < SL; cc += 128)
            __stcs((float4*)(wbase + (size_t)r * SL + cc),
                   make_float4(0.f, 0.f, 0.f, 0.f));

    lsum[0] += __shfl_xor_sync(0xffffffffu, lsum[0], 1);
    lsum[0] += __shfl_xor_sync(0xffffffffu, lsum[0], 2);
    lsum[1] += __shfl_xor_sync(0xffffffffu, lsum[1], 1);
    lsum[1] += __shfl_xor_sync(0xffffffffu, lsum[1], 2);
    float inv_l[2] = {1.f / lsum[0], 1.f / lsum[1]};

    if (tg == 0) {
        size_t lb = (size_t)(b * NH + h) * SL + q0;
        l_out[lb + wm + g]     = lsum[0];
        l_out[lb + wm + g + 8] = lsum[1];
    }

    // write o scaled by 1/l, tf32-pre-rounded (proj GEMM reads it raw)
#pragma unroll
    for (int nt = 0; nt < 8; nt++) {
        int cold = nt * 8 + 2 * tg;
        size_t r0o = (size_t)((size_t)b * SL + q0 + wm + g) * DM + h * HD + cold;
        size_t r1o = (size_t)((size_t)b * SL + q0 + wm + g + 8) * DM + h * HD + cold;
        *(float2*)(o_out + r0o) = make_float2(to_tf32(o[nt][0] * inv_l[0]),
                                              to_tf32(o[nt][1] * inv_l[0]));
        *(float2*)(o_out + r1o) = make_float2(to_tf32(o[nt][2] * inv_l[1]),
                                              to_tf32(o[nt][3] * inv_l[1]));
    }
}

// ---------------------------------------------------------------------------
// Normalize w rows by 1/l — 2 rows per 256-thr block, streaming ld/st.
// ---------------------------------------------------------------------------
__global__ __launch_bounds__(256) void norm_kernel(
    float* __restrict__ w, const float* __restrict__ l)
{
    int row = blockIdx.x * 2 + (threadIdx.x >> 7);
    int t = threadIdx.x & 127;
    int q = row & (SL - 1);
    float inv = 1.f / l[row];
    int ncols = ((q >> 6) + 1) << 6;
    float* wr = w + (size_t)row * SL;
    for (int c = t * 4; c < ncols; c += 512) {
        float4 v = __ldcs((const float4*)(wr + c));
        v.x *= inv; v.y *= inv; v.z *= inv; v.w *= inv;
        __stcs((float4*)(wr + c), v);
    }
}

// ---------------------------------------------------------------------------
extern "C" void kernel_launch(void* const* d_in, const int* in_sizes, int n_in,
                              void* d_out, int out_size)
{
    const float* x      = (const float*)d_in[0];  // (2,2048,1024)
    const float* w_qkv  = (const float*)d_in[1];  // (1024,3072)
    const float* w_proj = (const float*)d_in[2];  // (1024,1024)
    float* out    = (float*)d_out;                 // (2,2048,1024)
    float* w_attn = out + (size_t)MR * DM;         // (2,16,2048,2048)

    float *qkvp, *op, *xr, *wT, *lp, *vt;
    uint32_t *khi, *klo;
    cudaGetSymbolAddress((void**)&qkvp, g_qkv);
    cudaGetSymbolAddress((void**)&op,   g_o);
    cudaGetSymbolAddress((void**)&xr,   g_xr);
    cudaGetSymbolAddress((void**)&wT,   g_wT);
    cudaGetSymbolAddress((void**)&lp,   g_l);
    cudaGetSymbolAddress((void**)&khi,  g_khi);
    cudaGetSymbolAddress((void**)&klo,  g_klo);
    cudaGetSymbolAddress((void**)&vt,   g_vt);
    float* wprojT = wT + (size_t)3 * DM * DM;

    cudaFuncSetAttribute(mma_gemm2,
                         cudaFuncAttributeMaxDynamicSharedMemorySize, GEMM2_SMEM);
    cudaFuncSetAttribute(attn_sp5,
                         cudaFuncAttributeMaxDynamicSharedMemorySize, ATTN_SMEM);

    // 0) prep: round x; round+transpose weights
    round_tf32_kernel<<<(MR * DM / 4 + 255) / 256, 256>>>(x, xr, MR * DM / 4);
    transpose_round32<<<dim3(3 * DM / 32, DM / 32), dim3(32, 8)>>>(w_qkv, wT, DM, 3 * DM);
    transpose_round32<<<dim3(DM / 32, DM / 32), dim3(32, 8)>>>(w_proj, wprojT, DM, DM);

    // 1) qkv = x @ w_qkv  (128x128 CTAs, 2 per SM)
    dim3 g1(3 * DM / 128, MR / 128);
    mma_gemm2<<<g1, 128, GEMM2_SMEM>>>(xr, wT, qkvp, MR, 3 * DM, DM);

    // 1.5) attention prep: split K, transpose V
    attn_prep<<<dim3(SL / 64, NH, BSZ), 256>>>(qkvp, khi, klo, vt);

    // 2) single-pass attention (q-block 128, 3-stage cp.async K/V staging)
    dim3 g2(SL / 128, NH, BSZ);
    attn_sp5<<<g2, 256, ATTN_SMEM>>>(qkvp, khi, klo, vt, w_attn, op, lp);

    // 3) normalize w rows
    norm_kernel<<<BSZ * NH * SL / 2, 256>>>(w_attn, lp);

    // 4) out = o @ w_proj  (128x128 CTAs, 2 per SM)
    dim3 g3(DM / 128, MR / 128);
    mma_gemm2<<<g3, 128, GEMM2_SMEM>>>(op, wprojT, out, MR, DM, DM);
}